// round 14
// baseline (speedup 1.0000x reference)
#include <cuda_runtime.h>
#include <cuda_fp16.h>
#include <cstdint>

// ---------------------------------------------------------------------------
// Het_GNN forward — fp16 mma.sync, BK=64 3-stage, 2 CTAs/SM, cp.async.cg,
// hw-tanh epilogue, fp16 intermediates, persistent-CTA LSTM kernels.
// ---------------------------------------------------------------------------
#define BB   512
#define MPU  12288
#define MT   25088
#define MI2  12800
#define EE   2000

__device__ __half g_in16 [51773440];
__device__ __half g_w16  [27111936];
__device__ __half g_bufX [25690112];
__device__ __half g_Ht16 [MT * EE];
__device__ float  g_Hc   [BB  * EE];
__device__ __half g_Hp16 [MPU * EE];
__device__ __half g_Hu16 [MPU * EE];
__device__ __half g_H2   [2 * MPU * EE];
__device__ __half g_Hm   [2 * BB * EE];
__device__ float  g_uagg [BB * EE];
__device__ float  g_pagg [BB * EE];

#define I_TEXT 0
#define I_IMG  19267584
#define I_OTH  45481984
#define X_TEXT 0
#define X_IMG  12845056
#define X_OTH  19398656
#define O_WLT   0
#define O_WLI   393216
#define O_WLO   1441792
#define O_LT    1703936      // 5 lstm gathers, stride 3072000
#define O_UALIN 17063936
#define O_PALIN 18087936
#define O_UAOUT 19111936
#define O_PAOUT 23111936

// ---------------- helpers ----------------------------------------------------
__device__ __forceinline__ float tanh_hw(float x) {
    float r;
    asm("tanh.approx.f32 %0, %1;" : "=f"(r) : "f"(x));
    return r;
}
__device__ __forceinline__ float sig_hw(float x) {
    return fmaf(0.5f, tanh_hw(0.5f * x), 0.5f);
}
__device__ __forceinline__ void mma_f16(float& d0, float& d1, float& d2, float& d3,
                                        unsigned a0, unsigned a1, unsigned a2, unsigned a3,
                                        unsigned b0, unsigned b1) {
    asm volatile(
        "mma.sync.aligned.m16n8k16.row.col.f32.f16.f16.f32 "
        "{%0,%1,%2,%3}, {%4,%5,%6,%7}, {%8,%9}, {%0,%1,%2,%3};"
        : "+f"(d0), "+f"(d1), "+f"(d2), "+f"(d3)
        : "r"(a0), "r"(a1), "r"(a2), "r"(a3), "r"(b0), "r"(b1));
}
__device__ __forceinline__ void ldsm4(unsigned& r0, unsigned& r1, unsigned& r2,
                                      unsigned& r3, uint32_t a) {
    asm volatile("ldmatrix.sync.aligned.m8n8.x4.shared.b16 {%0,%1,%2,%3}, [%4];"
                 : "=r"(r0), "=r"(r1), "=r"(r2), "=r"(r3) : "r"(a));
}
__device__ __forceinline__ void cpa16(uint32_t dst, const void* src, int srcbytes) {
    asm volatile("cp.async.cg.shared.global [%0], [%1], 16, %2;"
                 :: "r"(dst), "l"(src), "r"(srcbytes) : "memory");
}
__device__ __forceinline__ void cp_commit() {
    asm volatile("cp.async.commit_group;" ::: "memory");
}
template<int N>
__device__ __forceinline__ void cp_wait() {
    asm volatile("cp.async.wait_group %0;" :: "n"(N) : "memory");
}
__device__ __forceinline__ int gather_row(int n, int t) {
    int d = (n >= 1000);
    int toff = (t == 0) ? 0 : (t == 1 ? 2000 : 3000);
    return d * 4000 + toff + (n - d * 1000);
}

// ---------------- batched conversion kernels (1 group / thread) --------------
struct CvtSegs {
    const float* src[8];
    __half* dst[8];
    int n[8];
};
__global__ void cvt_many(CvtSegs cs) {
    const int z = blockIdx.z;
    const int n = cs.n[z];
    const int i = (blockIdx.x * blockDim.x + threadIdx.x) * 8;
    if (i >= n) return;
    const float* __restrict__ src = cs.src[z];
    __half* __restrict__ dst = cs.dst[z];
    float4 a = *(const float4*)(src + i);
    float4 b = *(const float4*)(src + i + 4);
    __half2 h[4] = { __floats2half2_rn(a.x, a.y), __floats2half2_rn(a.z, a.w),
                     __floats2half2_rn(b.x, b.y), __floats2half2_rn(b.z, b.w) };
    *(uint4*)(dst + i) = *(uint4*)h;
}
struct Lstm5 { const float* W[5]; };
__global__ void cvt_lstm5(Lstm5 ws, __half* __restrict__ base) {
    const int z = blockIdx.z;
    const int idx = (blockIdx.x * blockDim.x + threadIdx.x) * 8;
    if (idx >= 3 * 2000 * 512) return;
    const float* __restrict__ W = ws.W[z];
    __half* __restrict__ dst = base + O_LT + (size_t)z * 3072000;
    int k = idx & 511;
    int n = (idx >> 9) % 2000;
    int t = idx / (2000 * 512);
    const float* s = W + (size_t)gather_row(n, t) * 512 + k;
    float4 a = *(const float4*)s;
    float4 b = *(const float4*)(s + 4);
    __half2 h[4] = { __floats2half2_rn(a.x, a.y), __floats2half2_rn(a.z, a.w),
                     __floats2half2_rn(b.x, b.y), __floats2half2_rn(b.z, b.w) };
    *(uint4*)(dst + idx) = *(uint4*)h;
}

// ---------------- arg structs -------------------------------------------------
struct LinSet  { const __half* A; const __half* W; const float* bias;
                 float* Cf; __half* Ch; int M; int K; };
struct LstmSet { const __half* A; const __half* Wg; const float* bG;
                 const __half* Acc; float* Cf; __half* Ch;
                 int M; int splitM; };

// ===========================================================================
// gemm_lin16<OUT16>: C[M,N] = A[M,K] @ W[N,K]^T + bias
// BM=128, BN=128, BK=64, 256 thr (8 warps 2m x 4n), 3-stage. 2 CTAs/SM.
// ===========================================================================
#define L_TA 16384
#define L_STRIDE 32768
#define SMEM_GEMM (3 * 32768)

template<bool OUT16>
__global__ __launch_bounds__(256, 2) void gemm_lin16(
    LinSet s0, LinSet s1, LinSet s2, int N) {
    const LinSet S = (blockIdx.z == 0) ? s0 : (blockIdx.z == 1 ? s1 : s2);
    const int m0 = blockIdx.y * 128, n0 = blockIdx.x * 128;
    if (m0 >= S.M) return;
    const int K = S.K;

    extern __shared__ char sm[];
    const uint32_t smb = (uint32_t)__cvta_generic_to_shared(sm);

    const int tid = threadIdx.x;
    const int wid = tid >> 5, lane = tid & 31;
    const int wm = wid & 1, wn = wid >> 1;
    const int lr = lane >> 2, lc = lane & 3;

    const int prow = tid >> 3, pch = tid & 7;
    const __half* srcA[4];
    uint32_t dA[4];
#pragma unroll
    for (int p = 0; p < 4; p++) {
        int r = prow + 32 * p;
        srcA[p] = S.A + (size_t)(m0 + r) * K + pch * 8;
        dA[p] = smb + r * 128 + ((pch ^ (r & 7)) << 4);
    }
    const __half* srcB[4];
    uint32_t dB[4];
    bool brOK[4];
#pragma unroll
    for (int p = 0; p < 4; p++) {
        int r = prow + 32 * p;
        brOK[p] = (n0 + r) < N;
        srcB[p] = S.W + (size_t)(brOK[p] ? (n0 + r) : 0) * K + pch * 8;
        dB[p] = smb + L_TA + r * 128 + ((pch ^ (r & 7)) << 4);
    }

    const int l15 = lane & 15, hi = lane >> 4;
    uint32_t aOff[4], bOff[2];
    int aSwz[4], bSwz[2];
#pragma unroll
    for (int mi = 0; mi < 4; mi++) {
        int r = wm * 64 + mi * 16 + l15;
        aOff[mi] = r * 128; aSwz[mi] = r & 7;
    }
#pragma unroll
    for (int nj = 0; nj < 2; nj++) {
        int r = wn * 32 + nj * 16 + l15;
        bOff[nj] = L_TA + r * 128; bSwz[nj] = r & 7;
    }

    float acc[4][4][4];
#pragma unroll
    for (int mi = 0; mi < 4; mi++)
#pragma unroll
        for (int ni = 0; ni < 4; ni++)
#pragma unroll
            for (int r = 0; r < 4; r++) acc[mi][ni][r] = 0.0f;

    const int nt = (K + 63) >> 6;
    auto LOAD = [&](int st, int kt) {
        const uint32_t so = st * L_STRIDE;
        const int kb = (kt + pch * 8 + 8 <= K) ? 16 : 0;
#pragma unroll
        for (int p = 0; p < 4; p++) cpa16(dA[p] + so, srcA[p] + kt, kb);
#pragma unroll
        for (int p = 0; p < 4; p++) cpa16(dB[p] + so, srcB[p] + kt, brOK[p] ? kb : 0);
    };

    LOAD(0, 0); cp_commit();
    LOAD(1, 64); cp_commit();

    for (int i = 0; i < nt; i++) {
        cp_wait<1>();
        __syncthreads();
        if (i + 2 < nt) LOAD((i + 2) % 3, (i + 2) << 6);
        cp_commit();

        const uint32_t base = smb + (i % 3) * L_STRIDE;
#pragma unroll
        for (int s = 0; s < 4; s++) {
            const int ch = 2 * s + hi;
            unsigned af[4][4], bq[2][4];
#pragma unroll
            for (int mi = 0; mi < 4; mi++)
                ldsm4(af[mi][0], af[mi][1], af[mi][2], af[mi][3],
                      base + aOff[mi] + ((ch ^ aSwz[mi]) << 4));
#pragma unroll
            for (int nj = 0; nj < 2; nj++)
                ldsm4(bq[nj][0], bq[nj][1], bq[nj][2], bq[nj][3],
                      base + bOff[nj] + ((ch ^ bSwz[nj]) << 4));
#pragma unroll
            for (int mi = 0; mi < 4; mi++)
#pragma unroll
                for (int nj = 0; nj < 2; nj++) {
                    mma_f16(acc[mi][2 * nj][0], acc[mi][2 * nj][1],
                            acc[mi][2 * nj][2], acc[mi][2 * nj][3],
                            af[mi][0], af[mi][1], af[mi][2], af[mi][3],
                            bq[nj][0], bq[nj][2]);
                    mma_f16(acc[mi][2 * nj + 1][0], acc[mi][2 * nj + 1][1],
                            acc[mi][2 * nj + 1][2], acc[mi][2 * nj + 1][3],
                            af[mi][0], af[mi][1], af[mi][2], af[mi][3],
                            bq[nj][1], bq[nj][3]);
                }
        }
    }

#pragma unroll
    for (int mi = 0; mi < 4; mi++) {
        int m = m0 + wm * 64 + mi * 16 + lr;
#pragma unroll
        for (int ni = 0; ni < 4; ni++) {
            int n = n0 + wn * 32 + ni * 8 + lc * 2;
            if (n + 1 < N) {
                float b0 = S.bias[n], b1 = S.bias[n + 1];
                float v00 = acc[mi][ni][0] + b0, v01 = acc[mi][ni][1] + b1;
                float v10 = acc[mi][ni][2] + b0, v11 = acc[mi][ni][3] + b1;
                if (OUT16) {
                    *(__half2*)(S.Ch + (size_t)m * N + n) = __floats2half2_rn(v00, v01);
                    *(__half2*)(S.Ch + (size_t)(m + 8) * N + n) = __floats2half2_rn(v10, v11);
                } else {
                    *(float2*)(S.Cf + (size_t)m * N + n) = make_float2(v00, v01);
                    *(float2*)(S.Cf + (size_t)(m + 8) * N + n) = make_float2(v10, v11);
                }
            } else if (n < N) {
                float b0 = S.bias[n];
                if (OUT16) {
                    S.Ch[(size_t)m * N + n] = __float2half_rn(acc[mi][ni][0] + b0);
                    S.Ch[(size_t)(m + 8) * N + n] = __float2half_rn(acc[mi][ni][2] + b0);
                } else {
                    S.Cf[(size_t)m * N + n] = acc[mi][ni][0] + b0;
                    S.Cf[(size_t)(m + 8) * N + n] = acc[mi][ni][2] + b0;
                }
            }
        }
    }
}

// ===========================================================================
// gemm_lstm16<ACC>: fused single-step BiLSTM — PERSISTENT CTAs.
// Each CTA loops over tiles (stride P); cp.async pipeline runs continuously
// across tile boundaries; epilogue overlaps the next tile's first loads.
// BM=64, BN=64x3 gates, BK=64, 256 thr (8 warps 2m x 4n), 3-stage. K=512.
// ===========================================================================
#define S_TA 8192
#define S_STRIDE 32768

template<bool ACC>
__global__ __launch_bounds__(256, 2) void gemm_lstm16(
    LstmSet s0, LstmSet s1, float scale, int P) {
    const int N = 2000, K = 512;
    const LstmSet S = blockIdx.z ? s1 : s0;
    extern __shared__ char sm[];
    const uint32_t smb = (uint32_t)__cvta_generic_to_shared(sm);

    const int tid = threadIdx.x;
    const int wid = tid >> 5, lane = tid & 31;
    const int wm = wid & 1, wn = wid >> 1;
    const int lr = lane >> 2, lc = lane & 3;

    const int prow = tid >> 3, pch = tid & 7;
    // stage-0 smem destinations (fixed)
    uint32_t dA[2], dB[6];
#pragma unroll
    for (int p = 0; p < 2; p++) {
        int r = prow + 32 * p;
        dA[p] = smb + r * 128 + ((pch ^ (r & 7)) << 4);
    }
#pragma unroll
    for (int p = 0; p < 6; p++) {
        int r = prow + 32 * p;
        dB[p] = smb + S_TA + r * 128 + ((pch ^ (r & 7)) << 4);
    }

    const int l15 = lane & 15, hi = lane >> 4;
    uint32_t aOff[2]; int aSwz[2];
#pragma unroll
    for (int mi = 0; mi < 2; mi++) {
        int r = wm * 32 + mi * 16 + l15;
        aOff[mi] = r * 128; aSwz[mi] = r & 7;
    }
    uint32_t bOff[3]; int bSwz;
    {
        int r = wn * 16 + l15;
        bSwz = r & 7;
#pragma unroll
        for (int t = 0; t < 3; t++) bOff[t] = S_TA + (t * 64 + r) * 128;
    }

    const int T = (S.M >> 6) << 5;       // (M/64) * 32 n-tiles
    int tcur = blockIdx.x;
    if (tcur >= T) return;

    // per-tile gmem element offsets (32-bit) for producer
    uint32_t cA[2], cB[6]; unsigned cOk;
    uint32_t nAo[2], nBo[6]; unsigned nOk;
    auto calc = [&](int t, uint32_t* Ao, uint32_t* Bo, unsigned& okm) {
        int m0 = (t >> 5) << 6;
        int n0 = (t & 31) << 6;
#pragma unroll
        for (int p = 0; p < 2; p++)
            Ao[p] = (uint32_t)((m0 + prow + 32 * p) * K + pch * 8);
        okm = 0;
#pragma unroll
        for (int p = 0; p < 6; p++) {
            int r = prow + 32 * p;
            int tg = r >> 6, rr = r & 63;
            bool ok = (n0 + rr) < N;
            int row = tg * 2000 + (ok ? n0 + rr : 0);
            Bo[p] = (uint32_t)(row * K + pch * 8);
            okm |= (ok ? 1u : 0u) << p;
        }
    };
    calc(tcur, cA, cB, cOk);
    bool hasN = (tcur + P) < T;
    if (hasN) calc(tcur + P, nAo, nBo, nOk);

    auto LOADC = [&](int kt, int st) {
        uint32_t so = (uint32_t)st * S_STRIDE;
#pragma unroll
        for (int p = 0; p < 2; p++) cpa16(dA[p] + so, S.A + cA[p] + kt, 16);
#pragma unroll
        for (int p = 0; p < 6; p++)
            cpa16(dB[p] + so, S.Wg + cB[p] + kt, ((cOk >> p) & 1) ? 16 : 0);
    };
    auto LOADN = [&](int kt, int st) {
        uint32_t so = (uint32_t)st * S_STRIDE;
#pragma unroll
        for (int p = 0; p < 2; p++) cpa16(dA[p] + so, S.A + nAo[p] + kt, 16);
#pragma unroll
        for (int p = 0; p < 6; p++)
            cpa16(dB[p] + so, S.Wg + nBo[p] + kt, ((nOk >> p) & 1) ? 16 : 0);
    };

    LOADC(0, 0); cp_commit();
    LOADC(64, 1); cp_commit();
    int cs = 0;                           // comp stage (runs mod 3 continuously)

    float acc[3][2][2][4];

    for (;;) {
#pragma unroll
        for (int t = 0; t < 3; t++)
#pragma unroll
            for (int mi = 0; mi < 2; mi++)
#pragma unroll
                for (int ni = 0; ni < 2; ni++)
#pragma unroll
                    for (int r = 0; r < 4; r++) acc[t][mi][ni][r] = 0.0f;

        for (int i = 0; i < 8; i++) {
            cp_wait<1>();
            __syncthreads();
            int lst = cs + 2; if (lst >= 3) lst -= 3;
            if (i < 6) LOADC((i + 2) << 6, lst);
            else if (hasN) LOADN((i - 6) << 6, lst);
            cp_commit();

            const uint32_t base = smb + (uint32_t)cs * S_STRIDE;
#pragma unroll
            for (int s = 0; s < 4; s++) {
                const int ch = 2 * s + hi;
                unsigned af[2][4], bt[3][4];
#pragma unroll
                for (int mi = 0; mi < 2; mi++)
                    ldsm4(af[mi][0], af[mi][1], af[mi][2], af[mi][3],
                          base + aOff[mi] + ((ch ^ aSwz[mi]) << 4));
#pragma unroll
                for (int t = 0; t < 3; t++)
                    ldsm4(bt[t][0], bt[t][1], bt[t][2], bt[t][3],
                          base + bOff[t] + ((ch ^ bSwz) << 4));
#pragma unroll
                for (int t = 0; t < 3; t++)
#pragma unroll
                    for (int mi = 0; mi < 2; mi++) {
                        mma_f16(acc[t][mi][0][0], acc[t][mi][0][1],
                                acc[t][mi][0][2], acc[t][mi][0][3],
                                af[mi][0], af[mi][1], af[mi][2], af[mi][3],
                                bt[t][0], bt[t][2]);
                        mma_f16(acc[t][mi][1][0], acc[t][mi][1][1],
                                acc[t][mi][1][2], acc[t][mi][1][3],
                                af[mi][0], af[mi][1], af[mi][2], af[mi][3],
                                bt[t][1], bt[t][3]);
                    }
            }
            cs = (cs == 2) ? 0 : cs + 1;
        }

        // ---- epilogue for tile tcur (register-only; next tile's loads in flight)
        const int em0 = (tcur >> 5) << 6;
        const int en0 = (tcur & 31) << 6;
#pragma unroll
        for (int mi = 0; mi < 2; mi++)
#pragma unroll
            for (int ni = 0; ni < 2; ni++) {
                int mA = em0 + wm * 32 + mi * 16 + lr;
                int nA = en0 + wn * 16 + ni * 8 + lc * 2;
#pragma unroll
                for (int half = 0; half < 2; half++) {
                    int mm = mA + half * 8;
                    float o[2];
#pragma unroll
                    for (int q = 0; q < 2; q++) {
                        int r = half * 2 + q;
                        int nn = nA + q;
                        int d = (nn >= 1000);
                        int base = d * 4000 + (nn - d * 1000);
                        float gi = acc[0][mi][ni][r] + S.bG[base];
                        float gg = acc[1][mi][ni][r] + S.bG[base + 2000];
                        float go = acc[2][mi][ni][r] + S.bG[base + 3000];
                        float cc = sig_hw(gi) * tanh_hw(gg);
                        o[q] = scale * sig_hw(go) * tanh_hw(cc);
                    }
                    if (nA + 1 < N) {
                        if (ACC) {
                            float2 av = __half22float2(
                                *(const __half2*)(S.Acc + (size_t)mm * N + nA));
                            o[0] += av.x; o[1] += av.y;
                        }
                        if (mm < S.splitM)
                            *(float2*)(S.Cf + (size_t)mm * N + nA) = make_float2(o[0], o[1]);
                        else
                            *(__half2*)(S.Ch + (size_t)(mm - S.splitM) * N + nA) =
                                __floats2half2_rn(o[0], o[1]);
                    } else if (nA < N) {
                        float v = o[0];
                        if (ACC) v += __half2float(S.Acc[(size_t)mm * N + nA]);
                        if (mm < S.splitM) S.Cf[(size_t)mm * N + nA] = v;
                        else S.Ch[(size_t)(mm - S.splitM) * N + nA] = __float2half_rn(v);
                    }
                }
            }

        if (!hasN) break;
        tcur += P;
#pragma unroll
        for (int p = 0; p < 2; p++) cA[p] = nAo[p];
#pragma unroll
        for (int p = 0; p < 6; p++) cB[p] = nBo[p];
        cOk = nOk;
        hasN = (tcur + P) < T;
        if (hasN) calc(tcur + P, nAo, nBo, nOk);
    }
}

// ---------------- paired neighbor mean: vectorized ---------------------------
__global__ void mean16(const __half* __restrict__ Z, __half* __restrict__ out) {
    int idx = (blockIdx.x * blockDim.x + threadIdx.x) * 8;
    if (idx >= 2 * BB * EE) return;
    int bI = idx / EE, n = idx % EE;
    float s[8];
#pragma unroll
    for (int q = 0; q < 8; q++) s[q] = 0.f;
    const __half* base = Z + (size_t)bI * 24 * EE + n;
    for (int j = 0; j < 24; j++) {
        uint4 v = *(const uint4*)(base + (size_t)j * EE);
        const __half2* h = (const __half2*)&v;
#pragma unroll
        for (int q = 0; q < 4; q++) {
            float2 f = __half22float2(h[q]);
            s[2 * q] += f.x; s[2 * q + 1] += f.y;
        }
    }
    __half2 r[4];
#pragma unroll
    for (int q = 0; q < 4; q++)
        r[q] = __floats2half2_rn(s[2 * q] * (1.0f / 24.0f), s[2 * q + 1] * (1.0f / 24.0f));
    *(uint4*)(out + idx) = *(uint4*)r;
}

// ---------------- 3-way attention combine ------------------------------------
__global__ void attention_kernel(const float* __restrict__ c, const float* __restrict__ u,
                                 const float* __restrict__ p, const float* __restrict__ att,
                                 float* __restrict__ out) {
    int bI = blockIdx.x, tid = threadIdx.x;
    const float* cb = c + (size_t)bI * EE;
    const float* ub = u + (size_t)bI * EE;
    const float* pb = p + (size_t)bI * EE;
    float s0 = 0.f, s1 = 0.f, s2 = 0.f, s3 = 0.f;
    for (int n = tid; n < EE; n += 256) {
        float a0 = att[n], a1 = att[EE + n];
        float cv = cb[n];
        s0 += cv * a0;
        s1 += cv * a1;
        s2 += ub[n] * a1;
        s3 += pb[n] * a1;
    }
    __shared__ float red[4][256];
    red[0][tid] = s0; red[1][tid] = s1; red[2][tid] = s2; red[3][tid] = s3;
    __syncthreads();
    for (int s = 128; s > 0; s >>= 1) {
        if (tid < s) {
#pragma unroll
            for (int q = 0; q < 4; q++) red[q][tid] += red[q][tid + s];
        }
        __syncthreads();
    }
    __shared__ float w[3];
    if (tid == 0) {
        float sc[3];
        sc[0] = red[0][0] + red[1][0];
        sc[1] = red[0][0] + red[2][0];
        sc[2] = red[0][0] + red[3][0];
#pragma unroll
        for (int k = 0; k < 3; k++) sc[k] = sc[k] > 0.f ? sc[k] : 0.01f * sc[k];
        float mx = fmaxf(sc[0], fmaxf(sc[1], sc[2]));
        float e0 = __expf(sc[0] - mx), e1 = __expf(sc[1] - mx), e2 = __expf(sc[2] - mx);
        float inv = 1.0f / (e0 + e1 + e2);
        w[0] = e0 * inv; w[1] = e1 * inv; w[2] = e2 * inv;
    }
    __syncthreads();
    float w0 = w[0], w1 = w[1], w2 = w[2];
    for (int n = tid; n < EE; n += 256)
        out[(size_t)bI * EE + n] = w0 * cb[n] + w1 * ub[n] + w2 * pb[n];
}

// ---------------------------------------------------------------------------
extern "C" void kernel_launch(void* const* d_in, const int* in_sizes, int n_in,
                              void* d_out, int out_size) {
    const float* c_text  = (const float*)d_in[0];
    const float* c_image = (const float*)d_in[1];
    const float* p_text  = (const float*)d_in[2];
    const float* p_image = (const float*)d_in[3];
    const float* u_text  = (const float*)d_in[4];
    const float* u_other = (const float*)d_in[5];
    const float* W_lt = (const float*)d_in[6],  *b_lt = (const float*)d_in[7];
    const float* W_li = (const float*)d_in[8],  *b_li = (const float*)d_in[9];
    const float* W_lo = (const float*)d_in[10], *b_lo = (const float*)d_in[11];
    const float* lstm_t_W = (const float*)d_in[12], *lstm_t_b = (const float*)d_in[13];
    const float* lstm_i_W = (const float*)d_in[14], *lstm_i_b = (const float*)d_in[15];
    const float* lstm_o_W = (const float*)d_in[16], *lstm_o_b = (const float*)d_in[17];
    const float* ua_lin_W = (const float*)d_in[18], *ua_lin_b = (const float*)d_in[19];
    const float* ua_lstm_W = (const float*)d_in[20], *ua_lstm_b = (const float*)d_in[21];
    const float* ua_out_W = (const float*)d_in[22], *ua_out_b = (const float*)d_in[23];
    const float* pa_lin_W = (const float*)d_in[24], *pa_lin_b = (const float*)d_in[25];
    const float* pa_lstm_W = (const float*)d_in[26], *pa_lstm_b = (const float*)d_in[27];
    const float* pa_out_W = (const float*)d_in[28], *pa_out_b = (const float*)d_in[29];
    const float* p_att = (const float*)d_in[30];
    float* out = (float*)d_out;

    __half *in16, *w16, *bufX, *Ht16, *Hp16, *Hu16, *H2, *Hm;
    float *Hc, *uagg, *pagg;
    cudaGetSymbolAddress((void**)&in16, g_in16);
    cudaGetSymbolAddress((void**)&w16,  g_w16);
    cudaGetSymbolAddress((void**)&bufX, g_bufX);
    cudaGetSymbolAddress((void**)&Hc,   g_Hc);
    cudaGetSymbolAddress((void**)&Ht16, g_Ht16);
    cudaGetSymbolAddress((void**)&Hp16, g_Hp16);
    cudaGetSymbolAddress((void**)&Hu16, g_Hu16);
    cudaGetSymbolAddress((void**)&H2,   g_H2);
    cudaGetSymbolAddress((void**)&Hm,   g_Hm);
    cudaGetSymbolAddress((void**)&uagg, g_uagg);
    cudaGetSymbolAddress((void**)&pagg, g_pagg);

    cudaFuncSetAttribute(gemm_lin16<true>,
                         cudaFuncAttributeMaxDynamicSharedMemorySize, SMEM_GEMM);
    cudaFuncSetAttribute(gemm_lin16<false>,
                         cudaFuncAttributeMaxDynamicSharedMemorySize, SMEM_GEMM);
    cudaFuncSetAttribute(gemm_lstm16<false>,
                         cudaFuncAttributeMaxDynamicSharedMemorySize, SMEM_GEMM);
    cudaFuncSetAttribute(gemm_lstm16<true>,
                         cudaFuncAttributeMaxDynamicSharedMemorySize, SMEM_GEMM);

    // ---- 1: weight linears (7 segs) ----
    {
        CvtSegs cs{};
        cs.src[0] = W_lt;     cs.dst[0] = w16 + O_WLT;   cs.n[0] = 512 * 768;
        cs.src[1] = W_li;     cs.dst[1] = w16 + O_WLI;   cs.n[1] = 512 * 2048;
        cs.src[2] = W_lo;     cs.dst[2] = w16 + O_WLO;   cs.n[2] = 512 * 512;
        cs.src[3] = ua_lin_W; cs.dst[3] = w16 + O_UALIN; cs.n[3] = 512 * 2000;
        cs.src[4] = pa_lin_W; cs.dst[4] = w16 + O_PALIN; cs.n[4] = 512 * 2000;
        cs.src[5] = ua_out_W; cs.dst[5] = w16 + O_UAOUT; cs.n[5] = 2000 * 2000;
        cs.src[6] = pa_out_W; cs.dst[6] = w16 + O_PAOUT; cs.n[6] = 2000 * 2000;
        int gx = (2000 * 2000 / 8 + 255) / 256;
        cvt_many<<<dim3(gx, 1, 7), 256>>>(cs);
    }
    // ---- 2: lstm weight gathers (5 via z) ----
    {
        Lstm5 ws{ { lstm_t_W, lstm_i_W, lstm_o_W, ua_lstm_W, pa_lstm_W } };
        int gx = (3 * 2000 * 512 / 8 + 255) / 256;
        cvt_lstm5<<<dim3(gx, 1, 5), 256>>>(ws, w16);
    }
    // ---- 3: inputs (6 segs) ----
    {
        CvtSegs cs{};
        cs.src[0] = c_text;  cs.dst[0] = in16 + I_TEXT;                    cs.n[0] = BB * 768;
        cs.src[1] = p_text;  cs.dst[1] = in16 + I_TEXT + BB * 768;         cs.n[1] = MPU * 768;
        cs.src[2] = u_text;  cs.dst[2] = in16 + I_TEXT + (BB + MPU) * 768; cs.n[2] = MPU * 768;
        cs.src[3] = c_image; cs.dst[3] = in16 + I_IMG;                     cs.n[3] = BB * 2048;
        cs.src[4] = p_image; cs.dst[4] = in16 + I_IMG + BB * 2048;         cs.n[4] = MPU * 2048;
        cs.src[5] = u_other; cs.dst[5] = in16 + I_OTH;                     cs.n[5] = MPU * 512;
        int gx = (MPU * 2048 / 8 + 255) / 256;
        cvt_many<<<dim3(gx, 1, 6), 256>>>(cs);
    }

    // ---- 4: all three input linears, one z=3 launch (N=512) ----
    {
        LinSet a{in16 + I_TEXT, w16 + O_WLT, b_lt, nullptr, bufX + X_TEXT, MT, 768};
        LinSet b{in16 + I_IMG,  w16 + O_WLI, b_li, nullptr, bufX + X_IMG,  MI2, 2048};
        LinSet c{in16 + I_OTH,  w16 + O_WLO, b_lo, nullptr, bufX + X_OTH,  MPU, 512};
        gemm_lin16<true><<<dim3(4, MT / 128, 3), 256, SMEM_GEMM>>>(a, b, c, 512);
    }
    // ---- 5: text LSTM -> Ht16 fp16 (persistent, 296 CTAs) ----
    {
        LstmSet t{bufX + X_TEXT, w16 + O_LT, lstm_t_b, nullptr, nullptr, Ht16,
                  MT, 0};
        gemm_lstm16<false><<<dim3(296, 1, 1), 256, SMEM_GEMM>>>(t, t, 0.5f, 296);
    }
    // ---- 6: image LSTM (split Hc/Hp16) + other LSTM (Hu16), z=2, persistent --
    {
        LstmSet im{bufX + X_IMG, w16 + O_LT + 1 * 3072000, lstm_i_b, Ht16,
                   Hc, Hp16, MI2, BB};
        LstmSet ot{bufX + X_OTH, w16 + O_LT + 2 * 3072000, lstm_o_b,
                   Ht16 + (size_t)MI2 * EE, nullptr, Hu16, MPU, 0};
        gemm_lstm16<true><<<dim3(148, 1, 2), 256, SMEM_GEMM>>>(im, ot, 0.5f, 148);
    }
    // ---- 7: paired agg linears (z=2, N=512, K=2000) ----
    {
        LinSet a{Hu16, w16 + O_UALIN, ua_lin_b, nullptr, bufX, MPU, 2000};
        LinSet b{Hp16, w16 + O_PALIN, pa_lin_b, nullptr, bufX + (size_t)MPU * 512,
                 MPU, 2000};
        gemm_lin16<true><<<dim3(4, MPU / 128, 2), 256, SMEM_GEMM>>>(a, b, b, 512);
    }
    // ---- 8: paired agg LSTMs (z=2, persistent) ----
    {
        LstmSet a{bufX, w16 + O_LT + 3 * 3072000, ua_lstm_b, nullptr, nullptr, H2,
                  MPU, 0};
        LstmSet b{bufX + (size_t)MPU * 512, w16 + O_LT + 4 * 3072000, pa_lstm_b,
                  nullptr, nullptr, H2 + (size_t)MPU * EE, MPU, 0};
        gemm_lstm16<false><<<dim3(148, 1, 2), 256, SMEM_GEMM>>>(a, b, 1.0f, 148);
    }
    // ---- 9: paired neighbor mean (vectorized) ----
    mean16<<<(2 * BB * EE / 8 + 255) / 256, 256>>>(H2, Hm);
    // ---- 10: paired out-linears (z=2, N=2000, fp32 out) ----
    {
        LinSet a{Hm, w16 + O_UAOUT, ua_out_b, uagg, nullptr, BB, 2000};
        LinSet b{Hm + (size_t)BB * EE, w16 + O_PAOUT, pa_out_b, pagg, nullptr,
                 BB, 2000};
        gemm_lin16<false><<<dim3(16, BB / 128, 2), 256, SMEM_GEMM>>>(a, b, b, 2000);
    }
    // ---- 11: attention combine ----
    attention_kernel<<<BB, 256>>>(Hc, uagg, pagg, p_att, out);
}

// round 15
// speedup vs baseline: 1.0494x; 1.0494x over previous
#include <cuda_runtime.h>
#include <cuda_fp16.h>
#include <cstdint>

// ---------------------------------------------------------------------------
// Het_GNN forward — fp16 mma.sync, BK=64 3-stage, 2 CTAs/SM, cp.async.cg,
// hw-tanh epilogue, fp16 intermediates. R13 structure + BM-templated lin.
// ---------------------------------------------------------------------------
#define BB   512
#define MPU  12288
#define MT   25088
#define MI2  12800
#define EE   2000

__device__ __half g_in16 [51773440];
__device__ __half g_w16  [27111936];
__device__ __half g_bufX [25690112];
__device__ __half g_Ht16 [MT * EE];
__device__ float  g_Hc   [BB  * EE];
__device__ __half g_Hp16 [MPU * EE];
__device__ __half g_Hu16 [MPU * EE];
__device__ __half g_H2   [2 * MPU * EE];
__device__ __half g_Hm   [2 * BB * EE];
__device__ float  g_uagg [BB * EE];
__device__ float  g_pagg [BB * EE];

#define I_TEXT 0
#define I_IMG  19267584
#define I_OTH  45481984
#define X_TEXT 0
#define X_IMG  12845056
#define X_OTH  19398656
#define O_WLT   0
#define O_WLI   393216
#define O_WLO   1441792
#define O_LT    1703936      // 5 lstm gathers, stride 3072000
#define O_UALIN 17063936
#define O_PALIN 18087936
#define O_UAOUT 19111936
#define O_PAOUT 23111936

// ---------------- helpers ----------------------------------------------------
__device__ __forceinline__ float tanh_hw(float x) {
    float r;
    asm("tanh.approx.f32 %0, %1;" : "=f"(r) : "f"(x));
    return r;
}
__device__ __forceinline__ float sig_hw(float x) {
    return fmaf(0.5f, tanh_hw(0.5f * x), 0.5f);
}
__device__ __forceinline__ void mma_f16(float& d0, float& d1, float& d2, float& d3,
                                        unsigned a0, unsigned a1, unsigned a2, unsigned a3,
                                        unsigned b0, unsigned b1) {
    asm volatile(
        "mma.sync.aligned.m16n8k16.row.col.f32.f16.f16.f32 "
        "{%0,%1,%2,%3}, {%4,%5,%6,%7}, {%8,%9}, {%0,%1,%2,%3};"
        : "+f"(d0), "+f"(d1), "+f"(d2), "+f"(d3)
        : "r"(a0), "r"(a1), "r"(a2), "r"(a3), "r"(b0), "r"(b1));
}
__device__ __forceinline__ void ldsm4(unsigned& r0, unsigned& r1, unsigned& r2,
                                      unsigned& r3, uint32_t a) {
    asm volatile("ldmatrix.sync.aligned.m8n8.x4.shared.b16 {%0,%1,%2,%3}, [%4];"
                 : "=r"(r0), "=r"(r1), "=r"(r2), "=r"(r3) : "r"(a));
}
__device__ __forceinline__ void cpa16(uint32_t dst, const void* src, int srcbytes) {
    asm volatile("cp.async.cg.shared.global [%0], [%1], 16, %2;"
                 :: "r"(dst), "l"(src), "r"(srcbytes) : "memory");
}
__device__ __forceinline__ void cp_commit() {
    asm volatile("cp.async.commit_group;" ::: "memory");
}
template<int N>
__device__ __forceinline__ void cp_wait() {
    asm volatile("cp.async.wait_group %0;" :: "n"(N) : "memory");
}
__device__ __forceinline__ int gather_row(int n, int t) {
    int d = (n >= 1000);
    int toff = (t == 0) ? 0 : (t == 1 ? 2000 : 3000);
    return d * 4000 + toff + (n - d * 1000);
}

// ---------------- batched conversion kernels (1 group / thread) --------------
struct CvtSegs {
    const float* src[13];
    __half* dst[13];
    int n[13];
};
__global__ void cvt_many(CvtSegs cs) {
    const int z = blockIdx.z;
    const int n = cs.n[z];
    const int i = (blockIdx.x * blockDim.x + threadIdx.x) * 8;
    if (i >= n) return;
    const float* __restrict__ src = cs.src[z];
    __half* __restrict__ dst = cs.dst[z];
    float4 a = *(const float4*)(src + i);
    float4 b = *(const float4*)(src + i + 4);
    __half2 h[4] = { __floats2half2_rn(a.x, a.y), __floats2half2_rn(a.z, a.w),
                     __floats2half2_rn(b.x, b.y), __floats2half2_rn(b.z, b.w) };
    *(uint4*)(dst + i) = *(uint4*)h;
}
struct Lstm5 { const float* W[5]; };
__global__ void cvt_lstm5(Lstm5 ws, __half* __restrict__ base) {
    const int z = blockIdx.z;
    const int idx = (blockIdx.x * blockDim.x + threadIdx.x) * 8;
    if (idx >= 3 * 2000 * 512) return;
    const float* __restrict__ W = ws.W[z];
    __half* __restrict__ dst = base + O_LT + (size_t)z * 3072000;
    int k = idx & 511;
    int n = (idx >> 9) % 2000;
    int t = idx / (2000 * 512);
    const float* s = W + (size_t)gather_row(n, t) * 512 + k;
    float4 a = *(const float4*)s;
    float4 b = *(const float4*)(s + 4);
    __half2 h[4] = { __floats2half2_rn(a.x, a.y), __floats2half2_rn(a.z, a.w),
                     __floats2half2_rn(b.x, b.y), __floats2half2_rn(b.z, b.w) };
    *(uint4*)(dst + idx) = *(uint4*)h;
}

// ---------------- arg structs -------------------------------------------------
struct LinSet  { const __half* A; const __half* W; const float* bias;
                 float* Cf; __half* Ch; int M; int K; };
struct LstmSet { const __half* A; const __half* Wg; const float* bG;
                 const __half* Acc; float* Cf; __half* Ch;
                 int M; int splitM; };

// ===========================================================================
// gemm_lin16<MI, OUT16>: C[M,N] = A[M,K] @ W[N,K]^T + bias
// BM = MI*32, BN=128, BK=64 (128B rows, chunk c of row m at c^(m&7)), 256 thr
// (8 warps 2m x 4n, warp tile (MI*16) x 32), 3-stage cp.async. 2 CTAs/SM.
// ===========================================================================
#define SMEM_LIN(MI) (3 * ((MI) * 32 + 128) * 128)

template<int MI, bool OUT16>
__global__ __launch_bounds__(256, 2) void gemm_lin16(
    LinSet s0, LinSet s1, LinSet s2, int N) {
    constexpr int BM = MI * 32;
    constexpr int TA = BM * 128;
    constexpr int STRIDE = TA + 128 * 128;

    const LinSet S = (blockIdx.z == 0) ? s0 : (blockIdx.z == 1 ? s1 : s2);
    const int m0 = blockIdx.y * BM, n0 = blockIdx.x * 128;
    if (m0 >= S.M) return;
    const int K = S.K;

    extern __shared__ char sm[];
    const uint32_t smb = (uint32_t)__cvta_generic_to_shared(sm);

    const int tid = threadIdx.x;
    const int wid = tid >> 5, lane = tid & 31;
    const int wm = wid & 1, wn = wid >> 1;
    const int lr = lane >> 2, lc = lane & 3;

    const int prow = tid >> 3, pch = tid & 7;
    const __half* srcA[MI];
    uint32_t dA[MI];
#pragma unroll
    for (int p = 0; p < MI; p++) {
        int r = prow + 32 * p;
        srcA[p] = S.A + (size_t)(m0 + r) * K + pch * 8;
        dA[p] = smb + r * 128 + ((pch ^ (r & 7)) << 4);
    }
    const __half* srcB[4];
    uint32_t dB[4];
    bool brOK[4];
#pragma unroll
    for (int p = 0; p < 4; p++) {
        int r = prow + 32 * p;
        brOK[p] = (n0 + r) < N;
        srcB[p] = S.W + (size_t)(brOK[p] ? (n0 + r) : 0) * K + pch * 8;
        dB[p] = smb + TA + r * 128 + ((pch ^ (r & 7)) << 4);
    }

    const int l15 = lane & 15, hi = lane >> 4;
    uint32_t aOff[MI], bOff[2];
    int aSwz[MI], bSwz[2];
#pragma unroll
    for (int mi = 0; mi < MI; mi++) {
        int r = wm * (MI * 16) + mi * 16 + l15;
        aOff[mi] = r * 128; aSwz[mi] = r & 7;
    }
#pragma unroll
    for (int nj = 0; nj < 2; nj++) {
        int r = wn * 32 + nj * 16 + l15;
        bOff[nj] = TA + r * 128; bSwz[nj] = r & 7;
    }

    float acc[MI][4][4];
#pragma unroll
    for (int mi = 0; mi < MI; mi++)
#pragma unroll
        for (int ni = 0; ni < 4; ni++)
#pragma unroll
            for (int r = 0; r < 4; r++) acc[mi][ni][r] = 0.0f;

    const int nt = (K + 63) >> 6;
    auto LOAD = [&](int st, int kt) {
        const uint32_t so = st * STRIDE;
        const int kb = (kt + pch * 8 + 8 <= K) ? 16 : 0;
#pragma unroll
        for (int p = 0; p < MI; p++) cpa16(dA[p] + so, srcA[p] + kt, kb);
#pragma unroll
        for (int p = 0; p < 4; p++) cpa16(dB[p] + so, srcB[p] + kt, brOK[p] ? kb : 0);
    };

    LOAD(0, 0); cp_commit();
    LOAD(1, 64); cp_commit();

    for (int i = 0; i < nt; i++) {
        cp_wait<1>();
        __syncthreads();
        if (i + 2 < nt) LOAD((i + 2) % 3, (i + 2) << 6);
        cp_commit();

        const uint32_t base = smb + (i % 3) * STRIDE;
#pragma unroll
        for (int s = 0; s < 4; s++) {
            const int ch = 2 * s + hi;
            unsigned af[MI][4], bq[2][4];
#pragma unroll
            for (int mi = 0; mi < MI; mi++)
                ldsm4(af[mi][0], af[mi][1], af[mi][2], af[mi][3],
                      base + aOff[mi] + ((ch ^ aSwz[mi]) << 4));
#pragma unroll
            for (int nj = 0; nj < 2; nj++)
                ldsm4(bq[nj][0], bq[nj][1], bq[nj][2], bq[nj][3],
                      base + bOff[nj] + ((ch ^ bSwz[nj]) << 4));
#pragma unroll
            for (int mi = 0; mi < MI; mi++)
#pragma unroll
                for (int nj = 0; nj < 2; nj++) {
                    mma_f16(acc[mi][2 * nj][0], acc[mi][2 * nj][1],
                            acc[mi][2 * nj][2], acc[mi][2 * nj][3],
                            af[mi][0], af[mi][1], af[mi][2], af[mi][3],
                            bq[nj][0], bq[nj][2]);
                    mma_f16(acc[mi][2 * nj + 1][0], acc[mi][2 * nj + 1][1],
                            acc[mi][2 * nj + 1][2], acc[mi][2 * nj + 1][3],
                            af[mi][0], af[mi][1], af[mi][2], af[mi][3],
                            bq[nj][1], bq[nj][3]);
                }
        }
    }

#pragma unroll
    for (int mi = 0; mi < MI; mi++) {
        int m = m0 + wm * (MI * 16) + mi * 16 + lr;
#pragma unroll
        for (int ni = 0; ni < 4; ni++) {
            int n = n0 + wn * 32 + ni * 8 + lc * 2;
            if (n + 1 < N) {
                float b0 = S.bias[n], b1 = S.bias[n + 1];
                float v00 = acc[mi][ni][0] + b0, v01 = acc[mi][ni][1] + b1;
                float v10 = acc[mi][ni][2] + b0, v11 = acc[mi][ni][3] + b1;
                if (OUT16) {
                    *(__half2*)(S.Ch + (size_t)m * N + n) = __floats2half2_rn(v00, v01);
                    *(__half2*)(S.Ch + (size_t)(m + 8) * N + n) = __floats2half2_rn(v10, v11);
                } else {
                    *(float2*)(S.Cf + (size_t)m * N + n) = make_float2(v00, v01);
                    *(float2*)(S.Cf + (size_t)(m + 8) * N + n) = make_float2(v10, v11);
                }
            } else if (n < N) {
                float b0 = S.bias[n];
                if (OUT16) {
                    S.Ch[(size_t)m * N + n] = __float2half_rn(acc[mi][ni][0] + b0);
                    S.Ch[(size_t)(m + 8) * N + n] = __float2half_rn(acc[mi][ni][2] + b0);
                } else {
                    S.Cf[(size_t)m * N + n] = acc[mi][ni][0] + b0;
                    S.Cf[(size_t)(m + 8) * N + n] = acc[mi][ni][2] + b0;
                }
            }
        }
    }
}

// ===========================================================================
// gemm_lstm16<ACC>: fused single-step BiLSTM (R13 version: frag double-buffer).
// BM=64, BN=64x3 gates, BK=64, 256 thr (8 warps 2m x 4n), 3-stage. K=512.
// ===========================================================================
#define S_TA 8192
#define S_STRIDE 32768
#define SMEM_LSTM (3 * 32768)

template<bool ACC>
__global__ __launch_bounds__(256, 2) void gemm_lstm16(
    LstmSet s0, LstmSet s1, float scale) {
    const int N = 2000, K = 512;
    const LstmSet S = blockIdx.z ? s1 : s0;
    const int m0 = blockIdx.y * 64, n0 = blockIdx.x * 64;
    if (m0 >= S.M) return;

    extern __shared__ char sm[];
    const uint32_t smb = (uint32_t)__cvta_generic_to_shared(sm);

    const int tid = threadIdx.x;
    const int wid = tid >> 5, lane = tid & 31;
    const int wm = wid & 1, wn = wid >> 1;
    const int lr = lane >> 2, lc = lane & 3;

    const int prow = tid >> 3, pch = tid & 7;
    const __half* srcA[2];
    uint32_t dA[2];
#pragma unroll
    for (int p = 0; p < 2; p++) {
        int r = prow + 32 * p;
        srcA[p] = S.A + (size_t)(m0 + r) * K + pch * 8;
        dA[p] = smb + r * 128 + ((pch ^ (r & 7)) << 4);
    }
    const __half* srcB[6];
    uint32_t dB[6];
    bool bOK[6];
#pragma unroll
    for (int p = 0; p < 6; p++) {
        int r = prow + 32 * p;
        int t = r >> 6, rr = r & 63;
        bOK[p] = (n0 + rr) < N;
        srcB[p] = S.Wg + (size_t)(t * 2000 + (bOK[p] ? n0 + rr : 0)) * K + pch * 8;
        dB[p] = smb + S_TA + r * 128 + ((pch ^ (r & 7)) << 4);
    }

    const int l15 = lane & 15, hi = lane >> 4;
    uint32_t aOff[2]; int aSwz[2];
#pragma unroll
    for (int mi = 0; mi < 2; mi++) {
        int r = wm * 32 + mi * 16 + l15;
        aOff[mi] = r * 128; aSwz[mi] = r & 7;
    }
    uint32_t bOff[3]; int bSwz;
    {
        int r = wn * 16 + l15;
        bSwz = r & 7;
#pragma unroll
        for (int t = 0; t < 3; t++) bOff[t] = S_TA + (t * 64 + r) * 128;
    }

    float acc[3][2][2][4];
#pragma unroll
    for (int t = 0; t < 3; t++)
#pragma unroll
        for (int mi = 0; mi < 2; mi++)
#pragma unroll
            for (int ni = 0; ni < 2; ni++)
#pragma unroll
                for (int r = 0; r < 4; r++) acc[t][mi][ni][r] = 0.0f;

    const int nt = K >> 6;
    auto LOAD = [&](int st, int kt) {
        const uint32_t so = st * S_STRIDE;
#pragma unroll
        for (int p = 0; p < 2; p++) cpa16(dA[p] + so, srcA[p] + kt, 16);
#pragma unroll
        for (int p = 0; p < 6; p++) cpa16(dB[p] + so, srcB[p] + kt, bOK[p] ? 16 : 0);
    };

    LOAD(0, 0); cp_commit();
    LOAD(1, 64); cp_commit();

    unsigned af[2][2][4], bt[2][3][4];

    for (int i = 0; i < nt; i++) {
        cp_wait<1>();
        __syncthreads();
        if (i + 2 < nt) LOAD((i + 2) % 3, (i + 2) << 6);
        cp_commit();

        const uint32_t base = smb + (i % 3) * S_STRIDE;
        {
            const int ch = hi;
#pragma unroll
            for (int mi = 0; mi < 2; mi++)
                ldsm4(af[0][mi][0], af[0][mi][1], af[0][mi][2], af[0][mi][3],
                      base + aOff[mi] + ((ch ^ aSwz[mi]) << 4));
#pragma unroll
            for (int t = 0; t < 3; t++)
                ldsm4(bt[0][t][0], bt[0][t][1], bt[0][t][2], bt[0][t][3],
                      base + bOff[t] + ((ch ^ bSwz) << 4));
        }
#pragma unroll
        for (int s = 0; s < 4; s++) {
            const int cur = s & 1, nxt = cur ^ 1;
            if (s < 3) {
                const int ch = 2 * (s + 1) + hi;
#pragma unroll
                for (int mi = 0; mi < 2; mi++)
                    ldsm4(af[nxt][mi][0], af[nxt][mi][1], af[nxt][mi][2], af[nxt][mi][3],
                          base + aOff[mi] + ((ch ^ aSwz[mi]) << 4));
#pragma unroll
                for (int t = 0; t < 3; t++)
                    ldsm4(bt[nxt][t][0], bt[nxt][t][1], bt[nxt][t][2], bt[nxt][t][3],
                          base + bOff[t] + ((ch ^ bSwz) << 4));
            }
#pragma unroll
            for (int t = 0; t < 3; t++)
#pragma unroll
                for (int mi = 0; mi < 2; mi++) {
                    mma_f16(acc[t][mi][0][0], acc[t][mi][0][1],
                            acc[t][mi][0][2], acc[t][mi][0][3],
                            af[cur][mi][0], af[cur][mi][1], af[cur][mi][2], af[cur][mi][3],
                            bt[cur][t][0], bt[cur][t][2]);
                    mma_f16(acc[t][mi][1][0], acc[t][mi][1][1],
                            acc[t][mi][1][2], acc[t][mi][1][3],
                            af[cur][mi][0], af[cur][mi][1], af[cur][mi][2], af[cur][mi][3],
                            bt[cur][t][1], bt[cur][t][3]);
                }
        }
    }

    // ---- hw-tanh epilogue, fp16 accum, split stores --------------------------
#pragma unroll
    for (int mi = 0; mi < 2; mi++)
#pragma unroll
        for (int ni = 0; ni < 2; ni++) {
            int mA = m0 + wm * 32 + mi * 16 + lr;
            int nA = n0 + wn * 16 + ni * 8 + lc * 2;
#pragma unroll
            for (int half = 0; half < 2; half++) {
                int mm = mA + half * 8;
                float o[2];
#pragma unroll
                for (int q = 0; q < 2; q++) {
                    int r = half * 2 + q;
                    int nn = nA + q;
                    int d = (nn >= 1000);
                    int base = d * 4000 + (nn - d * 1000);
                    float gi = acc[0][mi][ni][r] + S.bG[base];
                    float gg = acc[1][mi][ni][r] + S.bG[base + 2000];
                    float go = acc[2][mi][ni][r] + S.bG[base + 3000];
                    float cc = sig_hw(gi) * tanh_hw(gg);
                    o[q] = scale * sig_hw(go) * tanh_hw(cc);
                }
                if (nA + 1 < N) {
                    if (ACC) {
                        float2 av = __half22float2(
                            *(const __half2*)(S.Acc + (size_t)mm * N + nA));
                        o[0] += av.x; o[1] += av.y;
                    }
                    if (mm < S.splitM)
                        *(float2*)(S.Cf + (size_t)mm * N + nA) = make_float2(o[0], o[1]);
                    else
                        *(__half2*)(S.Ch + (size_t)(mm - S.splitM) * N + nA) =
                            __floats2half2_rn(o[0], o[1]);
                } else if (nA < N) {
                    float v = o[0];
                    if (ACC) v += __half2float(S.Acc[(size_t)mm * N + nA]);
                    if (mm < S.splitM) S.Cf[(size_t)mm * N + nA] = v;
                    else S.Ch[(size_t)(mm - S.splitM) * N + nA] = __float2half_rn(v);
                }
            }
        }
}

// ---------------- paired neighbor mean: vectorized ---------------------------
__global__ void mean16(const __half* __restrict__ Z, __half* __restrict__ out) {
    int idx = (blockIdx.x * blockDim.x + threadIdx.x) * 8;
    if (idx >= 2 * BB * EE) return;
    int bI = idx / EE, n = idx % EE;
    float s[8];
#pragma unroll
    for (int q = 0; q < 8; q++) s[q] = 0.f;
    const __half* base = Z + (size_t)bI * 24 * EE + n;
    for (int j = 0; j < 24; j++) {
        uint4 v = *(const uint4*)(base + (size_t)j * EE);
        const __half2* h = (const __half2*)&v;
#pragma unroll
        for (int q = 0; q < 4; q++) {
            float2 f = __half22float2(h[q]);
            s[2 * q] += f.x; s[2 * q + 1] += f.y;
        }
    }
    __half2 r[4];
#pragma unroll
    for (int q = 0; q < 4; q++)
        r[q] = __floats2half2_rn(s[2 * q] * (1.0f / 24.0f), s[2 * q + 1] * (1.0f / 24.0f));
    *(uint4*)(out + idx) = *(uint4*)r;
}

// ---------------- 3-way attention combine ------------------------------------
__global__ void attention_kernel(const float* __restrict__ c, const float* __restrict__ u,
                                 const float* __restrict__ p, const float* __restrict__ att,
                                 float* __restrict__ out) {
    int bI = blockIdx.x, tid = threadIdx.x;
    const float* cb = c + (size_t)bI * EE;
    const float* ub = u + (size_t)bI * EE;
    const float* pb = p + (size_t)bI * EE;
    float s0 = 0.f, s1 = 0.f, s2 = 0.f, s3 = 0.f;
    for (int n = tid; n < EE; n += 256) {
        float a0 = att[n], a1 = att[EE + n];
        float cv = cb[n];
        s0 += cv * a0;
        s1 += cv * a1;
        s2 += ub[n] * a1;
        s3 += pb[n] * a1;
    }
    __shared__ float red[4][256];
    red[0][tid] = s0; red[1][tid] = s1; red[2][tid] = s2; red[3][tid] = s3;
    __syncthreads();
    for (int s = 128; s > 0; s >>= 1) {
        if (tid < s) {
#pragma unroll
            for (int q = 0; q < 4; q++) red[q][tid] += red[q][tid + s];
        }
        __syncthreads();
    }
    __shared__ float w[3];
    if (tid == 0) {
        float sc[3];
        sc[0] = red[0][0] + red[1][0];
        sc[1] = red[0][0] + red[2][0];
        sc[2] = red[0][0] + red[3][0];
#pragma unroll
        for (int k = 0; k < 3; k++) sc[k] = sc[k] > 0.f ? sc[k] : 0.01f * sc[k];
        float mx = fmaxf(sc[0], fmaxf(sc[1], sc[2]));
        float e0 = __expf(sc[0] - mx), e1 = __expf(sc[1] - mx), e2 = __expf(sc[2] - mx);
        float inv = 1.0f / (e0 + e1 + e2);
        w[0] = e0 * inv; w[1] = e1 * inv; w[2] = e2 * inv;
    }
    __syncthreads();
    float w0 = w[0], w1 = w[1], w2 = w[2];
    for (int n = tid; n < EE; n += 256)
        out[(size_t)bI * EE + n] = w0 * cb[n] + w1 * ub[n] + w2 * pb[n];
}

// ---------------------------------------------------------------------------
extern "C" void kernel_launch(void* const* d_in, const int* in_sizes, int n_in,
                              void* d_out, int out_size) {
    const float* c_text  = (const float*)d_in[0];
    const float* c_image = (const float*)d_in[1];
    const float* p_text  = (const float*)d_in[2];
    const float* p_image = (const float*)d_in[3];
    const float* u_text  = (const float*)d_in[4];
    const float* u_other = (const float*)d_in[5];
    const float* W_lt = (const float*)d_in[6],  *b_lt = (const float*)d_in[7];
    const float* W_li = (const float*)d_in[8],  *b_li = (const float*)d_in[9];
    const float* W_lo = (const float*)d_in[10], *b_lo = (const float*)d_in[11];
    const float* lstm_t_W = (const float*)d_in[12], *lstm_t_b = (const float*)d_in[13];
    const float* lstm_i_W = (const float*)d_in[14], *lstm_i_b = (const float*)d_in[15];
    const float* lstm_o_W = (const float*)d_in[16], *lstm_o_b = (const float*)d_in[17];
    const float* ua_lin_W = (const float*)d_in[18], *ua_lin_b = (const float*)d_in[19];
    const float* ua_lstm_W = (const float*)d_in[20], *ua_lstm_b = (const float*)d_in[21];
    const float* ua_out_W = (const float*)d_in[22], *ua_out_b = (const float*)d_in[23];
    const float* pa_lin_W = (const float*)d_in[24], *pa_lin_b = (const float*)d_in[25];
    const float* pa_lstm_W = (const float*)d_in[26], *pa_lstm_b = (const float*)d_in[27];
    const float* pa_out_W = (const float*)d_in[28], *pa_out_b = (const float*)d_in[29];
    const float* p_att = (const float*)d_in[30];
    float* out = (float*)d_out;

    __half *in16, *w16, *bufX, *Ht16, *Hp16, *Hu16, *H2, *Hm;
    float *Hc, *uagg, *pagg;
    cudaGetSymbolAddress((void**)&in16, g_in16);
    cudaGetSymbolAddress((void**)&w16,  g_w16);
    cudaGetSymbolAddress((void**)&bufX, g_bufX);
    cudaGetSymbolAddress((void**)&Hc,   g_Hc);
    cudaGetSymbolAddress((void**)&Ht16, g_Ht16);
    cudaGetSymbolAddress((void**)&Hp16, g_Hp16);
    cudaGetSymbolAddress((void**)&Hu16, g_Hu16);
    cudaGetSymbolAddress((void**)&H2,   g_H2);
    cudaGetSymbolAddress((void**)&Hm,   g_Hm);
    cudaGetSymbolAddress((void**)&uagg, g_uagg);
    cudaGetSymbolAddress((void**)&pagg, g_pagg);

    cudaFuncSetAttribute(gemm_lin16<4, true>,
                         cudaFuncAttributeMaxDynamicSharedMemorySize, SMEM_LIN(4));
    cudaFuncSetAttribute(gemm_lin16<2, false>,
                         cudaFuncAttributeMaxDynamicSharedMemorySize, SMEM_LIN(2));
    cudaFuncSetAttribute(gemm_lstm16<false>,
                         cudaFuncAttributeMaxDynamicSharedMemorySize, SMEM_LSTM);
    cudaFuncSetAttribute(gemm_lstm16<true>,
                         cudaFuncAttributeMaxDynamicSharedMemorySize, SMEM_LSTM);

    // ---- 1: all flat fp16 conversions (13 segs, one launch) ----
    {
        CvtSegs cs{};
        cs.src[0]  = W_lt;     cs.dst[0]  = w16 + O_WLT;   cs.n[0]  = 512 * 768;
        cs.src[1]  = W_li;     cs.dst[1]  = w16 + O_WLI;   cs.n[1]  = 512 * 2048;
        cs.src[2]  = W_lo;     cs.dst[2]  = w16 + O_WLO;   cs.n[2]  = 512 * 512;
        cs.src[3]  = ua_lin_W; cs.dst[3]  = w16 + O_UALIN; cs.n[3]  = 512 * 2000;
        cs.src[4]  = pa_lin_W; cs.dst[4]  = w16 + O_PALIN; cs.n[4]  = 512 * 2000;
        cs.src[5]  = ua_out_W; cs.dst[5]  = w16 + O_UAOUT; cs.n[5]  = 2000 * 2000;
        cs.src[6]  = pa_out_W; cs.dst[6]  = w16 + O_PAOUT; cs.n[6]  = 2000 * 2000;
        cs.src[7]  = c_text;   cs.dst[7]  = in16 + I_TEXT;                    cs.n[7]  = BB * 768;
        cs.src[8]  = p_text;   cs.dst[8]  = in16 + I_TEXT + BB * 768;         cs.n[8]  = MPU * 768;
        cs.src[9]  = u_text;   cs.dst[9]  = in16 + I_TEXT + (BB + MPU) * 768; cs.n[9]  = MPU * 768;
        cs.src[10] = c_image;  cs.dst[10] = in16 + I_IMG;                     cs.n[10] = BB * 2048;
        cs.src[11] = p_image;  cs.dst[11] = in16 + I_IMG + BB * 2048;         cs.n[11] = MPU * 2048;
        cs.src[12] = u_other;  cs.dst[12] = in16 + I_OTH;                     cs.n[12] = MPU * 512;
        int gx = (MPU * 2048 / 8 + 255) / 256;
        cvt_many<<<dim3(gx, 1, 13), 256>>>(cs);
    }
    // ---- 2: lstm weight gathers (5 via z) ----
    {
        Lstm5 ws{ { lstm_t_W, lstm_i_W, lstm_o_W, ua_lstm_W, pa_lstm_W } };
        int gx = (3 * 2000 * 512 / 8 + 255) / 256;
        cvt_lstm5<<<dim3(gx, 1, 5), 256>>>(ws, w16);
    }

    // ---- 3: all three input linears, one z=3 launch (N=512) ----
    {
        LinSet a{in16 + I_TEXT, w16 + O_WLT, b_lt, nullptr, bufX + X_TEXT, MT, 768};
        LinSet b{in16 + I_IMG,  w16 + O_WLI, b_li, nullptr, bufX + X_IMG,  MI2, 2048};
        LinSet c{in16 + I_OTH,  w16 + O_WLO, b_lo, nullptr, bufX + X_OTH,  MPU, 512};
        gemm_lin16<4, true><<<dim3(4, MT / 128, 3), 256, SMEM_LIN(4)>>>(a, b, c, 512);
    }
    // ---- 4: text LSTM -> Ht16 fp16 ----
    {
        LstmSet t{bufX + X_TEXT, w16 + O_LT, lstm_t_b, nullptr, nullptr, Ht16,
                  MT, 0};
        gemm_lstm16<false><<<dim3(32, MT / 64, 1), 256, SMEM_LSTM>>>(t, t, 0.5f);
    }
    // ---- 5: image LSTM (split Hc/Hp16) + other LSTM (Hu16), z=2, fp16 accum --
    {
        LstmSet im{bufX + X_IMG, w16 + O_LT + 1 * 3072000, lstm_i_b, Ht16,
                   Hc, Hp16, MI2, BB};
        LstmSet ot{bufX + X_OTH, w16 + O_LT + 2 * 3072000, lstm_o_b,
                   Ht16 + (size_t)MI2 * EE, nullptr, Hu16, MPU, 0};
        gemm_lstm16<true><<<dim3(32, MI2 / 64, 2), 256, SMEM_LSTM>>>(im, ot, 0.5f);
    }
    // ---- 6: paired agg linears (z=2, N=512, K=2000) ----
    {
        LinSet a{Hu16, w16 + O_UALIN, ua_lin_b, nullptr, bufX, MPU, 2000};
        LinSet b{Hp16, w16 + O_PALIN, pa_lin_b, nullptr, bufX + (size_t)MPU * 512,
                 MPU, 2000};
        gemm_lin16<4, true><<<dim3(4, MPU / 128, 2), 256, SMEM_LIN(4)>>>(a, b, b, 512);
    }
    // ---- 7: paired agg LSTMs (z=2) ----
    {
        LstmSet a{bufX, w16 + O_LT + 3 * 3072000, ua_lstm_b, nullptr, nullptr, H2,
                  MPU, 0};
        LstmSet b{bufX + (size_t)MPU * 512, w16 + O_LT + 4 * 3072000, pa_lstm_b,
                  nullptr, nullptr, H2 + (size_t)MPU * EE, MPU, 0};
        gemm_lstm16<false><<<dim3(32, MPU / 64, 2), 256, SMEM_LSTM>>>(a, b, 1.0f);
    }
    // ---- 8: paired neighbor mean (vectorized) ----
    mean16<<<(2 * BB * EE / 8 + 255) / 256, 256>>>(H2, Hm);
    // ---- 9: paired out-linears (z=2, N=2000, fp32 out, BM=64 for grid fill) --
    {
        LinSet a{Hm, w16 + O_UAOUT, ua_out_b, uagg, nullptr, BB, 2000};
        LinSet b{Hm + (size_t)BB * EE, w16 + O_PAOUT, pa_out_b, pagg, nullptr,
                 BB, 2000};
        gemm_lin16<2, false><<<dim3(16, BB / 64, 2), 256, SMEM_LIN(2)>>>(a, b, b, 2000);
    }
    // ---- 10: attention combine ----
    attention_kernel<<<BB, 256>>>(Hc, uagg, pagg, p_att, out);
}

// round 16
// speedup vs baseline: 1.0886x; 1.0374x over previous
#include <cuda_runtime.h>
#include <cuda_fp16.h>
#include <cstdint>

// ---------------------------------------------------------------------------
// Het_GNN forward — fp16 mma.sync, BK=64 3-stage, 2 CTAs/SM, cp.async.cg,
// hw-tanh epilogue with smem-staged bias, fp16 intermediates. (R13 + bias-smem)
// ---------------------------------------------------------------------------
#define BB   512
#define MPU  12288
#define MT   25088
#define MI2  12800
#define EE   2000

__device__ __half g_in16 [51773440];
__device__ __half g_w16  [27111936];
__device__ __half g_bufX [25690112];
__device__ __half g_Ht16 [MT * EE];
__device__ float  g_Hc   [BB  * EE];
__device__ __half g_Hp16 [MPU * EE];
__device__ __half g_Hu16 [MPU * EE];
__device__ __half g_H2   [2 * MPU * EE];
__device__ __half g_Hm   [2 * BB * EE];
__device__ float  g_uagg [BB * EE];
__device__ float  g_pagg [BB * EE];

#define I_TEXT 0
#define I_IMG  19267584
#define I_OTH  45481984
#define X_TEXT 0
#define X_IMG  12845056
#define X_OTH  19398656
#define O_WLT   0
#define O_WLI   393216
#define O_WLO   1441792
#define O_LT    1703936      // 5 lstm gathers, stride 3072000
#define O_UALIN 17063936
#define O_PALIN 18087936
#define O_UAOUT 19111936
#define O_PAOUT 23111936

// ---------------- helpers ----------------------------------------------------
__device__ __forceinline__ float tanh_hw(float x) {
    float r;
    asm("tanh.approx.f32 %0, %1;" : "=f"(r) : "f"(x));
    return r;
}
__device__ __forceinline__ float sig_hw(float x) {
    return fmaf(0.5f, tanh_hw(0.5f * x), 0.5f);
}
__device__ __forceinline__ void mma_f16(float& d0, float& d1, float& d2, float& d3,
                                        unsigned a0, unsigned a1, unsigned a2, unsigned a3,
                                        unsigned b0, unsigned b1) {
    asm volatile(
        "mma.sync.aligned.m16n8k16.row.col.f32.f16.f16.f32 "
        "{%0,%1,%2,%3}, {%4,%5,%6,%7}, {%8,%9}, {%0,%1,%2,%3};"
        : "+f"(d0), "+f"(d1), "+f"(d2), "+f"(d3)
        : "r"(a0), "r"(a1), "r"(a2), "r"(a3), "r"(b0), "r"(b1));
}
__device__ __forceinline__ void ldsm4(unsigned& r0, unsigned& r1, unsigned& r2,
                                      unsigned& r3, uint32_t a) {
    asm volatile("ldmatrix.sync.aligned.m8n8.x4.shared.b16 {%0,%1,%2,%3}, [%4];"
                 : "=r"(r0), "=r"(r1), "=r"(r2), "=r"(r3) : "r"(a));
}
__device__ __forceinline__ void cpa16(uint32_t dst, const void* src, int srcbytes) {
    asm volatile("cp.async.cg.shared.global [%0], [%1], 16, %2;"
                 :: "r"(dst), "l"(src), "r"(srcbytes) : "memory");
}
__device__ __forceinline__ void cp_commit() {
    asm volatile("cp.async.commit_group;" ::: "memory");
}
template<int N>
__device__ __forceinline__ void cp_wait() {
    asm volatile("cp.async.wait_group %0;" :: "n"(N) : "memory");
}
__device__ __forceinline__ int gather_row(int n, int t) {
    int d = (n >= 1000);
    int toff = (t == 0) ? 0 : (t == 1 ? 2000 : 3000);
    return d * 4000 + toff + (n - d * 1000);
}

// ---------------- batched conversion kernels (1 group / thread) --------------
struct CvtSegs {
    const float* src[8];
    __half* dst[8];
    int n[8];
};
__global__ void cvt_many(CvtSegs cs) {
    const int z = blockIdx.z;
    const int n = cs.n[z];
    const int i = (blockIdx.x * blockDim.x + threadIdx.x) * 8;
    if (i >= n) return;
    const float* __restrict__ src = cs.src[z];
    __half* __restrict__ dst = cs.dst[z];
    float4 a = *(const float4*)(src + i);
    float4 b = *(const float4*)(src + i + 4);
    __half2 h[4] = { __floats2half2_rn(a.x, a.y), __floats2half2_rn(a.z, a.w),
                     __floats2half2_rn(b.x, b.y), __floats2half2_rn(b.z, b.w) };
    *(uint4*)(dst + i) = *(uint4*)h;
}
struct Lstm5 { const float* W[5]; };
__global__ void cvt_lstm5(Lstm5 ws, __half* __restrict__ base) {
    const int z = blockIdx.z;
    const int idx = (blockIdx.x * blockDim.x + threadIdx.x) * 8;
    if (idx >= 3 * 2000 * 512) return;
    const float* __restrict__ W = ws.W[z];
    __half* __restrict__ dst = base + O_LT + (size_t)z * 3072000;
    int k = idx & 511;
    int n = (idx >> 9) % 2000;
    int t = idx / (2000 * 512);
    const float* s = W + (size_t)gather_row(n, t) * 512 + k;
    float4 a = *(const float4*)s;
    float4 b = *(const float4*)(s + 4);
    __half2 h[4] = { __floats2half2_rn(a.x, a.y), __floats2half2_rn(a.z, a.w),
                     __floats2half2_rn(b.x, b.y), __floats2half2_rn(b.z, b.w) };
    *(uint4*)(dst + idx) = *(uint4*)h;
}

// ---------------- arg structs -------------------------------------------------
struct LinSet  { const __half* A; const __half* W; const float* bias;
                 float* Cf; __half* Ch; int M; int K; };
struct LstmSet { const __half* A; const __half* Wg; const float* bG;
                 const __half* Acc; float* Cf; __half* Ch;
                 int M; int splitM; };

// ===========================================================================
// gemm_lin16<OUT16>: C[M,N] = A[M,K] @ W[N,K]^T + bias
// BM=128, BN=128, BK=64, 256 thr (8 warps 2m x 4n), 3-stage. 2 CTAs/SM.
// ===========================================================================
#define L_TA 16384
#define L_STRIDE 32768
#define SMEM_GEMM (3 * 32768)

template<bool OUT16>
__global__ __launch_bounds__(256, 2) void gemm_lin16(
    LinSet s0, LinSet s1, LinSet s2, int N) {
    const LinSet S = (blockIdx.z == 0) ? s0 : (blockIdx.z == 1 ? s1 : s2);
    const int m0 = blockIdx.y * 128, n0 = blockIdx.x * 128;
    if (m0 >= S.M) return;
    const int K = S.K;

    extern __shared__ char sm[];
    const uint32_t smb = (uint32_t)__cvta_generic_to_shared(sm);

    const int tid = threadIdx.x;
    const int wid = tid >> 5, lane = tid & 31;
    const int wm = wid & 1, wn = wid >> 1;
    const int lr = lane >> 2, lc = lane & 3;

    const int prow = tid >> 3, pch = tid & 7;
    const __half* srcA[4];
    uint32_t dA[4];
#pragma unroll
    for (int p = 0; p < 4; p++) {
        int r = prow + 32 * p;
        srcA[p] = S.A + (size_t)(m0 + r) * K + pch * 8;
        dA[p] = smb + r * 128 + ((pch ^ (r & 7)) << 4);
    }
    const __half* srcB[4];
    uint32_t dB[4];
    bool brOK[4];
#pragma unroll
    for (int p = 0; p < 4; p++) {
        int r = prow + 32 * p;
        brOK[p] = (n0 + r) < N;
        srcB[p] = S.W + (size_t)(brOK[p] ? (n0 + r) : 0) * K + pch * 8;
        dB[p] = smb + L_TA + r * 128 + ((pch ^ (r & 7)) << 4);
    }

    const int l15 = lane & 15, hi = lane >> 4;
    uint32_t aOff[4], bOff[2];
    int aSwz[4], bSwz[2];
#pragma unroll
    for (int mi = 0; mi < 4; mi++) {
        int r = wm * 64 + mi * 16 + l15;
        aOff[mi] = r * 128; aSwz[mi] = r & 7;
    }
#pragma unroll
    for (int nj = 0; nj < 2; nj++) {
        int r = wn * 32 + nj * 16 + l15;
        bOff[nj] = L_TA + r * 128; bSwz[nj] = r & 7;
    }

    float acc[4][4][4];
#pragma unroll
    for (int mi = 0; mi < 4; mi++)
#pragma unroll
        for (int ni = 0; ni < 4; ni++)
#pragma unroll
            for (int r = 0; r < 4; r++) acc[mi][ni][r] = 0.0f;

    const int nt = (K + 63) >> 6;
    auto LOAD = [&](int st, int kt) {
        const uint32_t so = st * L_STRIDE;
        const int kb = (kt + pch * 8 + 8 <= K) ? 16 : 0;
#pragma unroll
        for (int p = 0; p < 4; p++) cpa16(dA[p] + so, srcA[p] + kt, kb);
#pragma unroll
        for (int p = 0; p < 4; p++) cpa16(dB[p] + so, srcB[p] + kt, brOK[p] ? kb : 0);
    };

    LOAD(0, 0); cp_commit();
    LOAD(1, 64); cp_commit();

    for (int i = 0; i < nt; i++) {
        cp_wait<1>();
        __syncthreads();
        if (i + 2 < nt) LOAD((i + 2) % 3, (i + 2) << 6);
        cp_commit();

        const uint32_t base = smb + (i % 3) * L_STRIDE;
#pragma unroll
        for (int s = 0; s < 4; s++) {
            const int ch = 2 * s + hi;
            unsigned af[4][4], bq[2][4];
#pragma unroll
            for (int mi = 0; mi < 4; mi++)
                ldsm4(af[mi][0], af[mi][1], af[mi][2], af[mi][3],
                      base + aOff[mi] + ((ch ^ aSwz[mi]) << 4));
#pragma unroll
            for (int nj = 0; nj < 2; nj++)
                ldsm4(bq[nj][0], bq[nj][1], bq[nj][2], bq[nj][3],
                      base + bOff[nj] + ((ch ^ bSwz[nj]) << 4));
#pragma unroll
            for (int mi = 0; mi < 4; mi++)
#pragma unroll
                for (int nj = 0; nj < 2; nj++) {
                    mma_f16(acc[mi][2 * nj][0], acc[mi][2 * nj][1],
                            acc[mi][2 * nj][2], acc[mi][2 * nj][3],
                            af[mi][0], af[mi][1], af[mi][2], af[mi][3],
                            bq[nj][0], bq[nj][2]);
                    mma_f16(acc[mi][2 * nj + 1][0], acc[mi][2 * nj + 1][1],
                            acc[mi][2 * nj + 1][2], acc[mi][2 * nj + 1][3],
                            af[mi][0], af[mi][1], af[mi][2], af[mi][3],
                            bq[nj][1], bq[nj][3]);
                }
        }
    }

#pragma unroll
    for (int mi = 0; mi < 4; mi++) {
        int m = m0 + wm * 64 + mi * 16 + lr;
#pragma unroll
        for (int ni = 0; ni < 4; ni++) {
            int n = n0 + wn * 32 + ni * 8 + lc * 2;
            if (n + 1 < N) {
                float b0 = S.bias[n], b1 = S.bias[n + 1];
                float v00 = acc[mi][ni][0] + b0, v01 = acc[mi][ni][1] + b1;
                float v10 = acc[mi][ni][2] + b0, v11 = acc[mi][ni][3] + b1;
                if (OUT16) {
                    *(__half2*)(S.Ch + (size_t)m * N + n) = __floats2half2_rn(v00, v01);
                    *(__half2*)(S.Ch + (size_t)(m + 8) * N + n) = __floats2half2_rn(v10, v11);
                } else {
                    *(float2*)(S.Cf + (size_t)m * N + n) = make_float2(v00, v01);
                    *(float2*)(S.Cf + (size_t)(m + 8) * N + n) = make_float2(v10, v11);
                }
            } else if (n < N) {
                float b0 = S.bias[n];
                if (OUT16) {
                    S.Ch[(size_t)m * N + n] = __float2half_rn(acc[mi][ni][0] + b0);
                    S.Ch[(size_t)(m + 8) * N + n] = __float2half_rn(acc[mi][ni][2] + b0);
                } else {
                    S.Cf[(size_t)m * N + n] = acc[mi][ni][0] + b0;
                    S.Cf[(size_t)(m + 8) * N + n] = acc[mi][ni][2] + b0;
                }
            }
        }
    }
}

// ===========================================================================
// gemm_lstm16<ACC>: fused single-step BiLSTM (frag double-buffer, smem bias).
// BM=64, BN=64x3 gates, BK=64, 256 thr (8 warps 2m x 4n), 3-stage. K=512.
// ===========================================================================
#define S_TA 8192
#define S_STRIDE 32768
#define SMEM_LSTM (3 * 32768 + 768)

template<bool ACC>
__global__ __launch_bounds__(256, 2) void gemm_lstm16(
    LstmSet s0, LstmSet s1, float scale) {
    const int N = 2000, K = 512;
    const LstmSet S = blockIdx.z ? s1 : s0;
    const int m0 = blockIdx.y * 64, n0 = blockIdx.x * 64;
    if (m0 >= S.M) return;

    extern __shared__ char sm[];
    const uint32_t smb = (uint32_t)__cvta_generic_to_shared(sm);
    float* sb = (float*)(sm + 3 * S_STRIDE);     // [3][64] staged bias

    const int tid = threadIdx.x;
    const int wid = tid >> 5, lane = tid & 31;
    const int wm = wid & 1, wn = wid >> 1;
    const int lr = lane >> 2, lc = lane & 3;

    // stage per-tile gate biases into smem (ordered by first __syncthreads)
    if (tid < 192) {
        int t = tid >> 6, j = tid & 63;
        int nn = n0 + j;
        float v = 0.f;
        if (nn < N) {
            int d = (nn >= 1000);
            int base = d * 4000 + (nn - d * 1000);
            v = S.bG[base + (t == 0 ? 0 : (t == 1 ? 2000 : 3000))];
        }
        sb[tid] = v;
    }

    const int prow = tid >> 3, pch = tid & 7;
    const __half* srcA[2];
    uint32_t dA[2];
#pragma unroll
    for (int p = 0; p < 2; p++) {
        int r = prow + 32 * p;
        srcA[p] = S.A + (size_t)(m0 + r) * K + pch * 8;
        dA[p] = smb + r * 128 + ((pch ^ (r & 7)) << 4);
    }
    const __half* srcB[6];
    uint32_t dB[6];
    bool bOK[6];
#pragma unroll
    for (int p = 0; p < 6; p++) {
        int r = prow + 32 * p;
        int t = r >> 6, rr = r & 63;
        bOK[p] = (n0 + rr) < N;
        srcB[p] = S.Wg + (size_t)(t * 2000 + (bOK[p] ? n0 + rr : 0)) * K + pch * 8;
        dB[p] = smb + S_TA + r * 128 + ((pch ^ (r & 7)) << 4);
    }

    const int l15 = lane & 15, hi = lane >> 4;
    uint32_t aOff[2]; int aSwz[2];
#pragma unroll
    for (int mi = 0; mi < 2; mi++) {
        int r = wm * 32 + mi * 16 + l15;
        aOff[mi] = r * 128; aSwz[mi] = r & 7;
    }
    uint32_t bOff[3]; int bSwz;
    {
        int r = wn * 16 + l15;
        bSwz = r & 7;
#pragma unroll
        for (int t = 0; t < 3; t++) bOff[t] = S_TA + (t * 64 + r) * 128;
    }

    float acc[3][2][2][4];
#pragma unroll
    for (int t = 0; t < 3; t++)
#pragma unroll
        for (int mi = 0; mi < 2; mi++)
#pragma unroll
            for (int ni = 0; ni < 2; ni++)
#pragma unroll
                for (int r = 0; r < 4; r++) acc[t][mi][ni][r] = 0.0f;

    const int nt = K >> 6;
    auto LOAD = [&](int st, int kt) {
        const uint32_t so = st * S_STRIDE;
#pragma unroll
        for (int p = 0; p < 2; p++) cpa16(dA[p] + so, srcA[p] + kt, 16);
#pragma unroll
        for (int p = 0; p < 6; p++) cpa16(dB[p] + so, srcB[p] + kt, bOK[p] ? 16 : 0);
    };

    LOAD(0, 0); cp_commit();
    LOAD(1, 64); cp_commit();

    unsigned af[2][2][4], bt[2][3][4];

    for (int i = 0; i < nt; i++) {
        cp_wait<1>();
        __syncthreads();
        if (i + 2 < nt) LOAD((i + 2) % 3, (i + 2) << 6);
        cp_commit();

        const uint32_t base = smb + (i % 3) * S_STRIDE;
        {
            const int ch = hi;
#pragma unroll
            for (int mi = 0; mi < 2; mi++)
                ldsm4(af[0][mi][0], af[0][mi][1], af[0][mi][2], af[0][mi][3],
                      base + aOff[mi] + ((ch ^ aSwz[mi]) << 4));
#pragma unroll
            for (int t = 0; t < 3; t++)
                ldsm4(bt[0][t][0], bt[0][t][1], bt[0][t][2], bt[0][t][3],
                      base + bOff[t] + ((ch ^ bSwz) << 4));
        }
#pragma unroll
        for (int s = 0; s < 4; s++) {
            const int cur = s & 1, nxt = cur ^ 1;
            if (s < 3) {
                const int ch = 2 * (s + 1) + hi;
#pragma unroll
                for (int mi = 0; mi < 2; mi++)
                    ldsm4(af[nxt][mi][0], af[nxt][mi][1], af[nxt][mi][2], af[nxt][mi][3],
                          base + aOff[mi] + ((ch ^ aSwz[mi]) << 4));
#pragma unroll
                for (int t = 0; t < 3; t++)
                    ldsm4(bt[nxt][t][0], bt[nxt][t][1], bt[nxt][t][2], bt[nxt][t][3],
                          base + bOff[t] + ((ch ^ bSwz) << 4));
            }
#pragma unroll
            for (int t = 0; t < 3; t++)
#pragma unroll
                for (int mi = 0; mi < 2; mi++) {
                    mma_f16(acc[t][mi][0][0], acc[t][mi][0][1],
                            acc[t][mi][0][2], acc[t][mi][0][3],
                            af[cur][mi][0], af[cur][mi][1], af[cur][mi][2], af[cur][mi][3],
                            bt[cur][t][0], bt[cur][t][2]);
                    mma_f16(acc[t][mi][1][0], acc[t][mi][1][1],
                            acc[t][mi][1][2], acc[t][mi][1][3],
                            af[cur][mi][0], af[cur][mi][1], af[cur][mi][2], af[cur][mi][3],
                            bt[cur][t][1], bt[cur][t][3]);
                }
        }
    }

    // ---- hw-tanh epilogue, smem bias, fp16 accum, split stores --------------
    const int nLoc0 = wn * 16 + lc * 2;         // tile-local n for ni=0
#pragma unroll
    for (int mi = 0; mi < 2; mi++)
#pragma unroll
        for (int ni = 0; ni < 2; ni++) {
            int mA = m0 + wm * 32 + mi * 16 + lr;
            int nL = nLoc0 + ni * 8;
            int nA = n0 + nL;
#pragma unroll
            for (int half = 0; half < 2; half++) {
                int mm = mA + half * 8;
                float o[2];
#pragma unroll
                for (int q = 0; q < 2; q++) {
                    int r = half * 2 + q;
                    float gi = acc[0][mi][ni][r] + sb[nL + q];
                    float gg = acc[1][mi][ni][r] + sb[64 + nL + q];
                    float go = acc[2][mi][ni][r] + sb[128 + nL + q];
                    float cc = sig_hw(gi) * tanh_hw(gg);
                    o[q] = scale * sig_hw(go) * tanh_hw(cc);
                }
                if (nA + 1 < N) {
                    if (ACC) {
                        float2 av = __half22float2(
                            *(const __half2*)(S.Acc + (size_t)mm * N + nA));
                        o[0] += av.x; o[1] += av.y;
                    }
                    if (mm < S.splitM)
                        *(float2*)(S.Cf + (size_t)mm * N + nA) = make_float2(o[0], o[1]);
                    else
                        *(__half2*)(S.Ch + (size_t)(mm - S.splitM) * N + nA) =
                            __floats2half2_rn(o[0], o[1]);
                } else if (nA < N) {
                    float v = o[0];
                    if (ACC) v += __half2float(S.Acc[(size_t)mm * N + nA]);
                    if (mm < S.splitM) S.Cf[(size_t)mm * N + nA] = v;
                    else S.Ch[(size_t)(mm - S.splitM) * N + nA] = __float2half_rn(v);
                }
            }
        }
}

// ---------------- paired neighbor mean: vectorized ---------------------------
__global__ void mean16(const __half* __restrict__ Z, __half* __restrict__ out) {
    int idx = (blockIdx.x * blockDim.x + threadIdx.x) * 8;
    if (idx >= 2 * BB * EE) return;
    int bI = idx / EE, n = idx % EE;
    float s[8];
#pragma unroll
    for (int q = 0; q < 8; q++) s[q] = 0.f;
    const __half* base = Z + (size_t)bI * 24 * EE + n;
    for (int j = 0; j < 24; j++) {
        uint4 v = *(const uint4*)(base + (size_t)j * EE);
        const __half2* h = (const __half2*)&v;
#pragma unroll
        for (int q = 0; q < 4; q++) {
            float2 f = __half22float2(h[q]);
            s[2 * q] += f.x; s[2 * q + 1] += f.y;
        }
    }
    __half2 r[4];
#pragma unroll
    for (int q = 0; q < 4; q++)
        r[q] = __floats2half2_rn(s[2 * q] * (1.0f / 24.0f), s[2 * q + 1] * (1.0f / 24.0f));
    *(uint4*)(out + idx) = *(uint4*)r;
}

// ---------------- 3-way attention combine ------------------------------------
__global__ void attention_kernel(const float* __restrict__ c, const float* __restrict__ u,
                                 const float* __restrict__ p, const float* __restrict__ att,
                                 float* __restrict__ out) {
    int bI = blockIdx.x, tid = threadIdx.x;
    const float* cb = c + (size_t)bI * EE;
    const float* ub = u + (size_t)bI * EE;
    const float* pb = p + (size_t)bI * EE;
    float s0 = 0.f, s1 = 0.f, s2 = 0.f, s3 = 0.f;
    for (int n = tid; n < EE; n += 256) {
        float a0 = att[n], a1 = att[EE + n];
        float cv = cb[n];
        s0 += cv * a0;
        s1 += cv * a1;
        s2 += ub[n] * a1;
        s3 += pb[n] * a1;
    }
    __shared__ float red[4][256];
    red[0][tid] = s0; red[1][tid] = s1; red[2][tid] = s2; red[3][tid] = s3;
    __syncthreads();
    for (int s = 128; s > 0; s >>= 1) {
        if (tid < s) {
#pragma unroll
            for (int q = 0; q < 4; q++) red[q][tid] += red[q][tid + s];
        }
        __syncthreads();
    }
    __shared__ float w[3];
    if (tid == 0) {
        float sc[3];
        sc[0] = red[0][0] + red[1][0];
        sc[1] = red[0][0] + red[2][0];
        sc[2] = red[0][0] + red[3][0];
#pragma unroll
        for (int k = 0; k < 3; k++) sc[k] = sc[k] > 0.f ? sc[k] : 0.01f * sc[k];
        float mx = fmaxf(sc[0], fmaxf(sc[1], sc[2]));
        float e0 = __expf(sc[0] - mx), e1 = __expf(sc[1] - mx), e2 = __expf(sc[2] - mx);
        float inv = 1.0f / (e0 + e1 + e2);
        w[0] = e0 * inv; w[1] = e1 * inv; w[2] = e2 * inv;
    }
    __syncthreads();
    float w0 = w[0], w1 = w[1], w2 = w[2];
    for (int n = tid; n < EE; n += 256)
        out[(size_t)bI * EE + n] = w0 * cb[n] + w1 * ub[n] + w2 * pb[n];
}

// ---------------------------------------------------------------------------
extern "C" void kernel_launch(void* const* d_in, const int* in_sizes, int n_in,
                              void* d_out, int out_size) {
    const float* c_text  = (const float*)d_in[0];
    const float* c_image = (const float*)d_in[1];
    const float* p_text  = (const float*)d_in[2];
    const float* p_image = (const float*)d_in[3];
    const float* u_text  = (const float*)d_in[4];
    const float* u_other = (const float*)d_in[5];
    const float* W_lt = (const float*)d_in[6],  *b_lt = (const float*)d_in[7];
    const float* W_li = (const float*)d_in[8],  *b_li = (const float*)d_in[9];
    const float* W_lo = (const float*)d_in[10], *b_lo = (const float*)d_in[11];
    const float* lstm_t_W = (const float*)d_in[12], *lstm_t_b = (const float*)d_in[13];
    const float* lstm_i_W = (const float*)d_in[14], *lstm_i_b = (const float*)d_in[15];
    const float* lstm_o_W = (const float*)d_in[16], *lstm_o_b = (const float*)d_in[17];
    const float* ua_lin_W = (const float*)d_in[18], *ua_lin_b = (const float*)d_in[19];
    const float* ua_lstm_W = (const float*)d_in[20], *ua_lstm_b = (const float*)d_in[21];
    const float* ua_out_W = (const float*)d_in[22], *ua_out_b = (const float*)d_in[23];
    const float* pa_lin_W = (const float*)d_in[24], *pa_lin_b = (const float*)d_in[25];
    const float* pa_lstm_W = (const float*)d_in[26], *pa_lstm_b = (const float*)d_in[27];
    const float* pa_out_W = (const float*)d_in[28], *pa_out_b = (const float*)d_in[29];
    const float* p_att = (const float*)d_in[30];
    float* out = (float*)d_out;

    __half *in16, *w16, *bufX, *Ht16, *Hp16, *Hu16, *H2, *Hm;
    float *Hc, *uagg, *pagg;
    cudaGetSymbolAddress((void**)&in16, g_in16);
    cudaGetSymbolAddress((void**)&w16,  g_w16);
    cudaGetSymbolAddress((void**)&bufX, g_bufX);
    cudaGetSymbolAddress((void**)&Hc,   g_Hc);
    cudaGetSymbolAddress((void**)&Ht16, g_Ht16);
    cudaGetSymbolAddress((void**)&Hp16, g_Hp16);
    cudaGetSymbolAddress((void**)&Hu16, g_Hu16);
    cudaGetSymbolAddress((void**)&H2,   g_H2);
    cudaGetSymbolAddress((void**)&Hm,   g_Hm);
    cudaGetSymbolAddress((void**)&uagg, g_uagg);
    cudaGetSymbolAddress((void**)&pagg, g_pagg);

    cudaFuncSetAttribute(gemm_lin16<true>,
                         cudaFuncAttributeMaxDynamicSharedMemorySize, SMEM_GEMM);
    cudaFuncSetAttribute(gemm_lin16<false>,
                         cudaFuncAttributeMaxDynamicSharedMemorySize, SMEM_GEMM);
    cudaFuncSetAttribute(gemm_lstm16<false>,
                         cudaFuncAttributeMaxDynamicSharedMemorySize, SMEM_LSTM);
    cudaFuncSetAttribute(gemm_lstm16<true>,
                         cudaFuncAttributeMaxDynamicSharedMemorySize, SMEM_LSTM);

    // ---- 1: weight linears (7 segs) ----
    {
        CvtSegs cs{};
        cs.src[0] = W_lt;     cs.dst[0] = w16 + O_WLT;   cs.n[0] = 512 * 768;
        cs.src[1] = W_li;     cs.dst[1] = w16 + O_WLI;   cs.n[1] = 512 * 2048;
        cs.src[2] = W_lo;     cs.dst[2] = w16 + O_WLO;   cs.n[2] = 512 * 512;
        cs.src[3] = ua_lin_W; cs.dst[3] = w16 + O_UALIN; cs.n[3] = 512 * 2000;
        cs.src[4] = pa_lin_W; cs.dst[4] = w16 + O_PALIN; cs.n[4] = 512 * 2000;
        cs.src[5] = ua_out_W; cs.dst[5] = w16 + O_UAOUT; cs.n[5] = 2000 * 2000;
        cs.src[6] = pa_out_W; cs.dst[6] = w16 + O_PAOUT; cs.n[6] = 2000 * 2000;
        int gx = (2000 * 2000 / 8 + 255) / 256;
        cvt_many<<<dim3(gx, 1, 7), 256>>>(cs);
    }
    // ---- 2: lstm weight gathers (5 via z) ----
    {
        Lstm5 ws{ { lstm_t_W, lstm_i_W, lstm_o_W, ua_lstm_W, pa_lstm_W } };
        int gx = (3 * 2000 * 512 / 8 + 255) / 256;
        cvt_lstm5<<<dim3(gx, 1, 5), 256>>>(ws, w16);
    }
    // ---- 3: inputs (6 segs) ----
    {
        CvtSegs cs{};
        cs.src[0] = c_text;  cs.dst[0] = in16 + I_TEXT;                    cs.n[0] = BB * 768;
        cs.src[1] = p_text;  cs.dst[1] = in16 + I_TEXT + BB * 768;         cs.n[1] = MPU * 768;
        cs.src[2] = u_text;  cs.dst[2] = in16 + I_TEXT + (BB + MPU) * 768; cs.n[2] = MPU * 768;
        cs.src[3] = c_image; cs.dst[3] = in16 + I_IMG;                     cs.n[3] = BB * 2048;
        cs.src[4] = p_image; cs.dst[4] = in16 + I_IMG + BB * 2048;         cs.n[4] = MPU * 2048;
        cs.src[5] = u_other; cs.dst[5] = in16 + I_OTH;                     cs.n[5] = MPU * 512;
        int gx = (MPU * 2048 / 8 + 255) / 256;
        cvt_many<<<dim3(gx, 1, 6), 256>>>(cs);
    }

    // ---- 4: all three input linears, one z=3 launch (N=512) ----
    {
        LinSet a{in16 + I_TEXT, w16 + O_WLT, b_lt, nullptr, bufX + X_TEXT, MT, 768};
        LinSet b{in16 + I_IMG,  w16 + O_WLI, b_li, nullptr, bufX + X_IMG,  MI2, 2048};
        LinSet c{in16 + I_OTH,  w16 + O_WLO, b_lo, nullptr, bufX + X_OTH,  MPU, 512};
        gemm_lin16<true><<<dim3(4, MT / 128, 3), 256, SMEM_GEMM>>>(a, b, c, 512);
    }
    // ---- 5: text LSTM -> Ht16 fp16 ----
    {
        LstmSet t{bufX + X_TEXT, w16 + O_LT, lstm_t_b, nullptr, nullptr, Ht16,
                  MT, 0};
        gemm_lstm16<false><<<dim3(32, MT / 64, 1), 256, SMEM_LSTM>>>(t, t, 0.5f);
    }
    // ---- 6: image LSTM (split Hc/Hp16) + other LSTM (Hu16), z=2, fp16 accum --
    {
        LstmSet im{bufX + X_IMG, w16 + O_LT + 1 * 3072000, lstm_i_b, Ht16,
                   Hc, Hp16, MI2, BB};
        LstmSet ot{bufX + X_OTH, w16 + O_LT + 2 * 3072000, lstm_o_b,
                   Ht16 + (size_t)MI2 * EE, nullptr, Hu16, MPU, 0};
        gemm_lstm16<true><<<dim3(32, MI2 / 64, 2), 256, SMEM_LSTM>>>(im, ot, 0.5f);
    }
    // ---- 7: paired agg linears (z=2, N=512, K=2000) ----
    {
        LinSet a{Hu16, w16 + O_UALIN, ua_lin_b, nullptr, bufX, MPU, 2000};
        LinSet b{Hp16, w16 + O_PALIN, pa_lin_b, nullptr, bufX + (size_t)MPU * 512,
                 MPU, 2000};
        gemm_lin16<true><<<dim3(4, MPU / 128, 2), 256, SMEM_GEMM>>>(a, b, b, 512);
    }
    // ---- 8: paired agg LSTMs (z=2) ----
    {
        LstmSet a{bufX, w16 + O_LT + 3 * 3072000, ua_lstm_b, nullptr, nullptr, H2,
                  MPU, 0};
        LstmSet b{bufX + (size_t)MPU * 512, w16 + O_LT + 4 * 3072000, pa_lstm_b,
                  nullptr, nullptr, H2 + (size_t)MPU * EE, MPU, 0};
        gemm_lstm16<false><<<dim3(32, MPU / 64, 2), 256, SMEM_LSTM>>>(a, b, 1.0f);
    }
    // ---- 9: paired neighbor mean (vectorized) ----
    mean16<<<(2 * BB * EE / 8 + 255) / 256, 256>>>(H2, Hm);
    // ---- 10: paired out-linears (z=2, N=2000, fp32 out) ----
    {
        LinSet a{Hm, w16 + O_UAOUT, ua_out_b, uagg, nullptr, BB, 2000};
        LinSet b{Hm + (size_t)BB * EE, w16 + O_PAOUT, pa_out_b, pagg, nullptr,
                 BB, 2000};
        gemm_lin16<false><<<dim3(16, BB / 128, 2), 256, SMEM_GEMM>>>(a, b, b, 2000);
    }
    // ---- 11: attention combine ----
    attention_kernel<<<BB, 256>>>(Hc, uagg, pagg, p_att, out);
}

// round 17
// speedup vs baseline: 1.1995x; 1.1019x over previous
#include <cuda_runtime.h>
#include <cuda_fp16.h>
#include <cstdint>

// ---------------------------------------------------------------------------
// Het_GNN forward — fp16 mma.sync, BK=64 3-stage, 2 CTAs/SM, cp.async.cg,
// hw-tanh epilogue + smem bias, precomputed LDSM addresses in the LSTM loop.
// ---------------------------------------------------------------------------
#define BB   512
#define MPU  12288
#define MT   25088
#define MI2  12800
#define EE   2000

__device__ __half g_in16 [51773440];
__device__ __half g_w16  [27111936];
__device__ __half g_bufX [25690112];
__device__ __half g_Ht16 [MT * EE];
__device__ float  g_Hc   [BB  * EE];
__device__ __half g_Hp16 [MPU * EE];
__device__ __half g_Hu16 [MPU * EE];
__device__ __half g_H2   [2 * MPU * EE];
__device__ __half g_Hm   [2 * BB * EE];
__device__ float  g_uagg [BB * EE];
__device__ float  g_pagg [BB * EE];

#define I_TEXT 0
#define I_IMG  19267584
#define I_OTH  45481984
#define X_TEXT 0
#define X_IMG  12845056
#define X_OTH  19398656
#define O_WLT   0
#define O_WLI   393216
#define O_WLO   1441792
#define O_LT    1703936      // 5 lstm gathers, stride 3072000
#define O_UALIN 17063936
#define O_PALIN 18087936
#define O_UAOUT 19111936
#define O_PAOUT 23111936

// ---------------- helpers ----------------------------------------------------
__device__ __forceinline__ float tanh_hw(float x) {
    float r;
    asm("tanh.approx.f32 %0, %1;" : "=f"(r) : "f"(x));
    return r;
}
__device__ __forceinline__ float sig_hw(float x) {
    return fmaf(0.5f, tanh_hw(0.5f * x), 0.5f);
}
__device__ __forceinline__ void mma_f16(float& d0, float& d1, float& d2, float& d3,
                                        unsigned a0, unsigned a1, unsigned a2, unsigned a3,
                                        unsigned b0, unsigned b1) {
    asm volatile(
        "mma.sync.aligned.m16n8k16.row.col.f32.f16.f16.f32 "
        "{%0,%1,%2,%3}, {%4,%5,%6,%7}, {%8,%9}, {%0,%1,%2,%3};"
        : "+f"(d0), "+f"(d1), "+f"(d2), "+f"(d3)
        : "r"(a0), "r"(a1), "r"(a2), "r"(a3), "r"(b0), "r"(b1));
}
__device__ __forceinline__ void ldsm4(unsigned& r0, unsigned& r1, unsigned& r2,
                                      unsigned& r3, uint32_t a) {
    asm volatile("ldmatrix.sync.aligned.m8n8.x4.shared.b16 {%0,%1,%2,%3}, [%4];"
                 : "=r"(r0), "=r"(r1), "=r"(r2), "=r"(r3) : "r"(a));
}
__device__ __forceinline__ void cpa16(uint32_t dst, const void* src, int srcbytes) {
    asm volatile("cp.async.cg.shared.global [%0], [%1], 16, %2;"
                 :: "r"(dst), "l"(src), "r"(srcbytes) : "memory");
}
__device__ __forceinline__ void cp_commit() {
    asm volatile("cp.async.commit_group;" ::: "memory");
}
template<int N>
__device__ __forceinline__ void cp_wait() {
    asm volatile("cp.async.wait_group %0;" :: "n"(N) : "memory");
}
__device__ __forceinline__ int gather_row(int n, int t) {
    int d = (n >= 1000);
    int toff = (t == 0) ? 0 : (t == 1 ? 2000 : 3000);
    return d * 4000 + toff + (n - d * 1000);
}

// ---------------- batched conversion kernels (1 group / thread) --------------
struct CvtSegs {
    const float* src[8];
    __half* dst[8];
    int n[8];
};
__global__ void cvt_many(CvtSegs cs) {
    const int z = blockIdx.z;
    const int n = cs.n[z];
    const int i = (blockIdx.x * blockDim.x + threadIdx.x) * 8;
    if (i >= n) return;
    const float* __restrict__ src = cs.src[z];
    __half* __restrict__ dst = cs.dst[z];
    float4 a = *(const float4*)(src + i);
    float4 b = *(const float4*)(src + i + 4);
    __half2 h[4] = { __floats2half2_rn(a.x, a.y), __floats2half2_rn(a.z, a.w),
                     __floats2half2_rn(b.x, b.y), __floats2half2_rn(b.z, b.w) };
    *(uint4*)(dst + i) = *(uint4*)h;
}
struct Lstm5 { const float* W[5]; };
__global__ void cvt_lstm5(Lstm5 ws, __half* __restrict__ base) {
    const int z = blockIdx.z;
    const int idx = (blockIdx.x * blockDim.x + threadIdx.x) * 8;
    if (idx >= 3 * 2000 * 512) return;
    const float* __restrict__ W = ws.W[z];
    __half* __restrict__ dst = base + O_LT + (size_t)z * 3072000;
    int k = idx & 511;
    int n = (idx >> 9) % 2000;
    int t = idx / (2000 * 512);
    const float* s = W + (size_t)gather_row(n, t) * 512 + k;
    float4 a = *(const float4*)s;
    float4 b = *(const float4*)(s + 4);
    __half2 h[4] = { __floats2half2_rn(a.x, a.y), __floats2half2_rn(a.z, a.w),
                     __floats2half2_rn(b.x, b.y), __floats2half2_rn(b.z, b.w) };
    *(uint4*)(dst + idx) = *(uint4*)h;
}

// ---------------- arg structs -------------------------------------------------
struct LinSet  { const __half* A; const __half* W; const float* bias;
                 float* Cf; __half* Ch; int M; int K; };
struct LstmSet { const __half* A; const __half* Wg; const float* bG;
                 const __half* Acc; float* Cf; __half* Ch;
                 int M; int splitM; };

// ===========================================================================
// gemm_lin16<OUT16>: C[M,N] = A[M,K] @ W[N,K]^T + bias
// BM=128, BN=128, BK=64, 256 thr (8 warps 2m x 4n), 3-stage. 2 CTAs/SM.
// ===========================================================================
#define L_TA 16384
#define L_STRIDE 32768
#define SMEM_GEMM (3 * 32768)

template<bool OUT16>
__global__ __launch_bounds__(256, 2) void gemm_lin16(
    LinSet s0, LinSet s1, LinSet s2, int N) {
    const LinSet S = (blockIdx.z == 0) ? s0 : (blockIdx.z == 1 ? s1 : s2);
    const int m0 = blockIdx.y * 128, n0 = blockIdx.x * 128;
    if (m0 >= S.M) return;
    const int K = S.K;

    extern __shared__ char sm[];
    const uint32_t smb = (uint32_t)__cvta_generic_to_shared(sm);

    const int tid = threadIdx.x;
    const int wid = tid >> 5, lane = tid & 31;
    const int wm = wid & 1, wn = wid >> 1;
    const int lr = lane >> 2, lc = lane & 3;

    const int prow = tid >> 3, pch = tid & 7;
    const __half* srcA[4];
    uint32_t dA[4];
#pragma unroll
    for (int p = 0; p < 4; p++) {
        int r = prow + 32 * p;
        srcA[p] = S.A + (size_t)(m0 + r) * K + pch * 8;
        dA[p] = smb + r * 128 + ((pch ^ (r & 7)) << 4);
    }
    const __half* srcB[4];
    uint32_t dB[4];
    bool brOK[4];
#pragma unroll
    for (int p = 0; p < 4; p++) {
        int r = prow + 32 * p;
        brOK[p] = (n0 + r) < N;
        srcB[p] = S.W + (size_t)(brOK[p] ? (n0 + r) : 0) * K + pch * 8;
        dB[p] = smb + L_TA + r * 128 + ((pch ^ (r & 7)) << 4);
    }

    const int l15 = lane & 15, hi = lane >> 4;
    uint32_t aOff[4], bOff[2];
    int aSwz[4], bSwz[2];
#pragma unroll
    for (int mi = 0; mi < 4; mi++) {
        int r = wm * 64 + mi * 16 + l15;
        aOff[mi] = r * 128; aSwz[mi] = r & 7;
    }
#pragma unroll
    for (int nj = 0; nj < 2; nj++) {
        int r = wn * 32 + nj * 16 + l15;
        bOff[nj] = L_TA + r * 128; bSwz[nj] = r & 7;
    }

    float acc[4][4][4];
#pragma unroll
    for (int mi = 0; mi < 4; mi++)
#pragma unroll
        for (int ni = 0; ni < 4; ni++)
#pragma unroll
            for (int r = 0; r < 4; r++) acc[mi][ni][r] = 0.0f;

    const int nt = (K + 63) >> 6;
    auto LOAD = [&](int st, int kt) {
        const uint32_t so = st * L_STRIDE;
        const int kb = (kt + pch * 8 + 8 <= K) ? 16 : 0;
#pragma unroll
        for (int p = 0; p < 4; p++) cpa16(dA[p] + so, srcA[p] + kt, kb);
#pragma unroll
        for (int p = 0; p < 4; p++) cpa16(dB[p] + so, srcB[p] + kt, brOK[p] ? kb : 0);
    };

    LOAD(0, 0); cp_commit();
    LOAD(1, 64); cp_commit();

    for (int i = 0; i < nt; i++) {
        cp_wait<1>();
        __syncthreads();
        if (i + 2 < nt) LOAD((i + 2) % 3, (i + 2) << 6);
        cp_commit();

        const uint32_t base = smb + (i % 3) * L_STRIDE;
#pragma unroll
        for (int s = 0; s < 4; s++) {
            const int ch = 2 * s + hi;
            unsigned af[4][4], bq[2][4];
#pragma unroll
            for (int mi = 0; mi < 4; mi++)
                ldsm4(af[mi][0], af[mi][1], af[mi][2], af[mi][3],
                      base + aOff[mi] + ((ch ^ aSwz[mi]) << 4));
#pragma unroll
            for (int nj = 0; nj < 2; nj++)
                ldsm4(bq[nj][0], bq[nj][1], bq[nj][2], bq[nj][3],
                      base + bOff[nj] + ((ch ^ bSwz[nj]) << 4));
#pragma unroll
            for (int mi = 0; mi < 4; mi++)
#pragma unroll
                for (int nj = 0; nj < 2; nj++) {
                    mma_f16(acc[mi][2 * nj][0], acc[mi][2 * nj][1],
                            acc[mi][2 * nj][2], acc[mi][2 * nj][3],
                            af[mi][0], af[mi][1], af[mi][2], af[mi][3],
                            bq[nj][0], bq[nj][2]);
                    mma_f16(acc[mi][2 * nj + 1][0], acc[mi][2 * nj + 1][1],
                            acc[mi][2 * nj + 1][2], acc[mi][2 * nj + 1][3],
                            af[mi][0], af[mi][1], af[mi][2], af[mi][3],
                            bq[nj][1], bq[nj][3]);
                }
        }
    }

#pragma unroll
    for (int mi = 0; mi < 4; mi++) {
        int m = m0 + wm * 64 + mi * 16 + lr;
#pragma unroll
        for (int ni = 0; ni < 4; ni++) {
            int n = n0 + wn * 32 + ni * 8 + lc * 2;
            if (n + 1 < N) {
                float b0 = S.bias[n], b1 = S.bias[n + 1];
                float v00 = acc[mi][ni][0] + b0, v01 = acc[mi][ni][1] + b1;
                float v10 = acc[mi][ni][2] + b0, v11 = acc[mi][ni][3] + b1;
                if (OUT16) {
                    *(__half2*)(S.Ch + (size_t)m * N + n) = __floats2half2_rn(v00, v01);
                    *(__half2*)(S.Ch + (size_t)(m + 8) * N + n) = __floats2half2_rn(v10, v11);
                } else {
                    *(float2*)(S.Cf + (size_t)m * N + n) = make_float2(v00, v01);
                    *(float2*)(S.Cf + (size_t)(m + 8) * N + n) = make_float2(v10, v11);
                }
            } else if (n < N) {
                float b0 = S.bias[n];
                if (OUT16) {
                    S.Ch[(size_t)m * N + n] = __float2half_rn(acc[mi][ni][0] + b0);
                    S.Ch[(size_t)(m + 8) * N + n] = __float2half_rn(acc[mi][ni][2] + b0);
                } else {
                    S.Cf[(size_t)m * N + n] = acc[mi][ni][0] + b0;
                    S.Cf[(size_t)(m + 8) * N + n] = acc[mi][ni][2] + b0;
                }
            }
        }
    }
}

// ===========================================================================
// gemm_lstm16<ACC>: fused single-step BiLSTM (smem bias, precomputed LDSM addrs).
// BM=64, BN=64x3 gates, BK=64, 256 thr (8 warps 2m x 4n), 3-stage. K=512.
// ===========================================================================
#define S_TA 8192
#define S_STRIDE 32768
#define SMEM_LSTM (3 * 32768 + 768)

template<bool ACC>
__global__ __launch_bounds__(256, 2) void gemm_lstm16(
    LstmSet s0, LstmSet s1, float scale) {
    const int N = 2000, K = 512;
    const LstmSet S = blockIdx.z ? s1 : s0;
    const int m0 = blockIdx.y * 64, n0 = blockIdx.x * 64;
    if (m0 >= S.M) return;

    extern __shared__ char sm[];
    const uint32_t smb = (uint32_t)__cvta_generic_to_shared(sm);
    float* sb = (float*)(sm + 3 * S_STRIDE);     // [3][64] staged bias

    const int tid = threadIdx.x;
    const int wid = tid >> 5, lane = tid & 31;
    const int wm = wid & 1, wn = wid >> 1;
    const int lr = lane >> 2, lc = lane & 3;

    // stage per-tile gate biases into smem (ordered by first __syncthreads)
    if (tid < 192) {
        int t = tid >> 6, j = tid & 63;
        int nn = n0 + j;
        float v = 0.f;
        if (nn < N) {
            int d = (nn >= 1000);
            int base = d * 4000 + (nn - d * 1000);
            v = S.bG[base + (t == 0 ? 0 : (t == 1 ? 2000 : 3000))];
        }
        sb[tid] = v;
    }

    const int prow = tid >> 3, pch = tid & 7;
    const __half* srcA[2];
    uint32_t dA[2];
#pragma unroll
    for (int p = 0; p < 2; p++) {
        int r = prow + 32 * p;
        srcA[p] = S.A + (size_t)(m0 + r) * K + pch * 8;
        dA[p] = smb + r * 128 + ((pch ^ (r & 7)) << 4);
    }
    const __half* srcB[6];
    uint32_t dB[6];
    bool bOK[6];
#pragma unroll
    for (int p = 0; p < 6; p++) {
        int r = prow + 32 * p;
        int t = r >> 6, rr = r & 63;
        bOK[p] = (n0 + rr) < N;
        srcB[p] = S.Wg + (size_t)(t * 2000 + (bOK[p] ? n0 + rr : 0)) * K + pch * 8;
        dB[p] = smb + S_TA + r * 128 + ((pch ^ (r & 7)) << 4);
    }

    // precomputed per-fragment, per-chunk-step smem offsets (base-independent)
    const int l15 = lane & 15, hi = lane >> 4;
    uint32_t offA[2][4], offB[3][4];
#pragma unroll
    for (int mi = 0; mi < 2; mi++) {
        int r = wm * 32 + mi * 16 + l15;
        uint32_t o = (uint32_t)r * 128;
        int sw = r & 7;
#pragma unroll
        for (int s = 0; s < 4; s++)
            offA[mi][s] = o + (uint32_t)(((2 * s + hi) ^ sw) << 4);
    }
    {
        int r = wn * 16 + l15;
        int sw = r & 7;
#pragma unroll
        for (int t = 0; t < 3; t++) {
            uint32_t o = S_TA + (uint32_t)(t * 64 + r) * 128;
#pragma unroll
            for (int s = 0; s < 4; s++)
                offB[t][s] = o + (uint32_t)(((2 * s + hi) ^ sw) << 4);
        }
    }

    float acc[3][2][2][4];
#pragma unroll
    for (int t = 0; t < 3; t++)
#pragma unroll
        for (int mi = 0; mi < 2; mi++)
#pragma unroll
            for (int ni = 0; ni < 2; ni++)
#pragma unroll
                for (int r = 0; r < 4; r++) acc[t][mi][ni][r] = 0.0f;

    const int nt = K >> 6;
    auto LOAD = [&](int st, int kt) {
        const uint32_t so = st * S_STRIDE;
#pragma unroll
        for (int p = 0; p < 2; p++) cpa16(dA[p] + so, srcA[p] + kt, 16);
#pragma unroll
        for (int p = 0; p < 6; p++) cpa16(dB[p] + so, srcB[p] + kt, bOK[p] ? 16 : 0);
    };

    LOAD(0, 0); cp_commit();
    LOAD(1, 64); cp_commit();

    for (int i = 0; i < nt; i++) {
        cp_wait<1>();
        __syncthreads();
        if (i + 2 < nt) LOAD((i + 2) % 3, (i + 2) << 6);
        cp_commit();

        const uint32_t base = smb + (i % 3) * S_STRIDE;
#pragma unroll
        for (int s = 0; s < 4; s++) {
            unsigned af[2][4], bt[3][4];
#pragma unroll
            for (int mi = 0; mi < 2; mi++)
                ldsm4(af[mi][0], af[mi][1], af[mi][2], af[mi][3],
                      base + offA[mi][s]);
#pragma unroll
            for (int t = 0; t < 3; t++)
                ldsm4(bt[t][0], bt[t][1], bt[t][2], bt[t][3],
                      base + offB[t][s]);
#pragma unroll
            for (int t = 0; t < 3; t++)
#pragma unroll
                for (int mi = 0; mi < 2; mi++) {
                    mma_f16(acc[t][mi][0][0], acc[t][mi][0][1],
                            acc[t][mi][0][2], acc[t][mi][0][3],
                            af[mi][0], af[mi][1], af[mi][2], af[mi][3],
                            bt[t][0], bt[t][2]);
                    mma_f16(acc[t][mi][1][0], acc[t][mi][1][1],
                            acc[t][mi][1][2], acc[t][mi][1][3],
                            af[mi][0], af[mi][1], af[mi][2], af[mi][3],
                            bt[t][1], bt[t][3]);
                }
        }
    }

    // ---- hw-tanh epilogue, smem bias, fp16 accum, split stores --------------
    const int nLoc0 = wn * 16 + lc * 2;
#pragma unroll
    for (int mi = 0; mi < 2; mi++)
#pragma unroll
        for (int ni = 0; ni < 2; ni++) {
            int mA = m0 + wm * 32 + mi * 16 + lr;
            int nL = nLoc0 + ni * 8;
            int nA = n0 + nL;
#pragma unroll
            for (int half = 0; half < 2; half++) {
                int mm = mA + half * 8;
                float o[2];
#pragma unroll
                for (int q = 0; q < 2; q++) {
                    int r = half * 2 + q;
                    float gi = acc[0][mi][ni][r] + sb[nL + q];
                    float gg = acc[1][mi][ni][r] + sb[64 + nL + q];
                    float go = acc[2][mi][ni][r] + sb[128 + nL + q];
                    float cc = sig_hw(gi) * tanh_hw(gg);
                    o[q] = scale * sig_hw(go) * tanh_hw(cc);
                }
                if (nA + 1 < N) {
                    if (ACC) {
                        float2 av = __half22float2(
                            *(const __half2*)(S.Acc + (size_t)mm * N + nA));
                        o[0] += av.x; o[1] += av.y;
                    }
                    if (mm < S.splitM)
                        *(float2*)(S.Cf + (size_t)mm * N + nA) = make_float2(o[0], o[1]);
                    else
                        *(__half2*)(S.Ch + (size_t)(mm - S.splitM) * N + nA) =
                            __floats2half2_rn(o[0], o[1]);
                } else if (nA < N) {
                    float v = o[0];
                    if (ACC) v += __half2float(S.Acc[(size_t)mm * N + nA]);
                    if (mm < S.splitM) S.Cf[(size_t)mm * N + nA] = v;
                    else S.Ch[(size_t)(mm - S.splitM) * N + nA] = __float2half_rn(v);
                }
            }
        }
}

// ---------------- paired neighbor mean: vectorized ---------------------------
__global__ void mean16(const __half* __restrict__ Z, __half* __restrict__ out) {
    int idx = (blockIdx.x * blockDim.x + threadIdx.x) * 8;
    if (idx >= 2 * BB * EE) return;
    int bI = idx / EE, n = idx % EE;
    float s[8];
#pragma unroll
    for (int q = 0; q < 8; q++) s[q] = 0.f;
    const __half* base = Z + (size_t)bI * 24 * EE + n;
    for (int j = 0; j < 24; j++) {
        uint4 v = *(const uint4*)(base + (size_t)j * EE);
        const __half2* h = (const __half2*)&v;
#pragma unroll
        for (int q = 0; q < 4; q++) {
            float2 f = __half22float2(h[q]);
            s[2 * q] += f.x; s[2 * q + 1] += f.y;
        }
    }
    __half2 r[4];
#pragma unroll
    for (int q = 0; q < 4; q++)
        r[q] = __floats2half2_rn(s[2 * q] * (1.0f / 24.0f), s[2 * q + 1] * (1.0f / 24.0f));
    *(uint4*)(out + idx) = *(uint4*)r;
}

// ---------------- 3-way attention combine ------------------------------------
__global__ void attention_kernel(const float* __restrict__ c, const float* __restrict__ u,
                                 const float* __restrict__ p, const float* __restrict__ att,
                                 float* __restrict__ out) {
    int bI = blockIdx.x, tid = threadIdx.x;
    const float* cb = c + (size_t)bI * EE;
    const float* ub = u + (size_t)bI * EE;
    const float* pb = p + (size_t)bI * EE;
    float s0 = 0.f, s1 = 0.f, s2 = 0.f, s3 = 0.f;
    for (int n = tid; n < EE; n += 256) {
        float a0 = att[n], a1 = att[EE + n];
        float cv = cb[n];
        s0 += cv * a0;
        s1 += cv * a1;
        s2 += ub[n] * a1;
        s3 += pb[n] * a1;
    }
    __shared__ float red[4][256];
    red[0][tid] = s0; red[1][tid] = s1; red[2][tid] = s2; red[3][tid] = s3;
    __syncthreads();
    for (int s = 128; s > 0; s >>= 1) {
        if (tid < s) {
#pragma unroll
            for (int q = 0; q < 4; q++) red[q][tid] += red[q][tid + s];
        }
        __syncthreads();
    }
    __shared__ float w[3];
    if (tid == 0) {
        float sc[3];
        sc[0] = red[0][0] + red[1][0];
        sc[1] = red[0][0] + red[2][0];
        sc[2] = red[0][0] + red[3][0];
#pragma unroll
        for (int k = 0; k < 3; k++) sc[k] = sc[k] > 0.f ? sc[k] : 0.01f * sc[k];
        float mx = fmaxf(sc[0], fmaxf(sc[1], sc[2]));
        float e0 = __expf(sc[0] - mx), e1 = __expf(sc[1] - mx), e2 = __expf(sc[2] - mx);
        float inv = 1.0f / (e0 + e1 + e2);
        w[0] = e0 * inv; w[1] = e1 * inv; w[2] = e2 * inv;
    }
    __syncthreads();
    float w0 = w[0], w1 = w[1], w2 = w[2];
    for (int n = tid; n < EE; n += 256)
        out[(size_t)bI * EE + n] = w0 * cb[n] + w1 * ub[n] + w2 * pb[n];
}

// ---------------------------------------------------------------------------
extern "C" void kernel_launch(void* const* d_in, const int* in_sizes, int n_in,
                              void* d_out, int out_size) {
    const float* c_text  = (const float*)d_in[0];
    const float* c_image = (const float*)d_in[1];
    const float* p_text  = (const float*)d_in[2];
    const float* p_image = (const float*)d_in[3];
    const float* u_text  = (const float*)d_in[4];
    const float* u_other = (const float*)d_in[5];
    const float* W_lt = (const float*)d_in[6],  *b_lt = (const float*)d_in[7];
    const float* W_li = (const float*)d_in[8],  *b_li = (const float*)d_in[9];
    const float* W_lo = (const float*)d_in[10], *b_lo = (const float*)d_in[11];
    const float* lstm_t_W = (const float*)d_in[12], *lstm_t_b = (const float*)d_in[13];
    const float* lstm_i_W = (const float*)d_in[14], *lstm_i_b = (const float*)d_in[15];
    const float* lstm_o_W = (const float*)d_in[16], *lstm_o_b = (const float*)d_in[17];
    const float* ua_lin_W = (const float*)d_in[18], *ua_lin_b = (const float*)d_in[19];
    const float* ua_lstm_W = (const float*)d_in[20], *ua_lstm_b = (const float*)d_in[21];
    const float* ua_out_W = (const float*)d_in[22], *ua_out_b = (const float*)d_in[23];
    const float* pa_lin_W = (const float*)d_in[24], *pa_lin_b = (const float*)d_in[25];
    const float* pa_lstm_W = (const float*)d_in[26], *pa_lstm_b = (const float*)d_in[27];
    const float* pa_out_W = (const float*)d_in[28], *pa_out_b = (const float*)d_in[29];
    const float* p_att = (const float*)d_in[30];
    float* out = (float*)d_out;

    __half *in16, *w16, *bufX, *Ht16, *Hp16, *Hu16, *H2, *Hm;
    float *Hc, *uagg, *pagg;
    cudaGetSymbolAddress((void**)&in16, g_in16);
    cudaGetSymbolAddress((void**)&w16,  g_w16);
    cudaGetSymbolAddress((void**)&bufX, g_bufX);
    cudaGetSymbolAddress((void**)&Hc,   g_Hc);
    cudaGetSymbolAddress((void**)&Ht16, g_Ht16);
    cudaGetSymbolAddress((void**)&Hp16, g_Hp16);
    cudaGetSymbolAddress((void**)&Hu16, g_Hu16);
    cudaGetSymbolAddress((void**)&H2,   g_H2);
    cudaGetSymbolAddress((void**)&Hm,   g_Hm);
    cudaGetSymbolAddress((void**)&uagg, g_uagg);
    cudaGetSymbolAddress((void**)&pagg, g_pagg);

    cudaFuncSetAttribute(gemm_lin16<true>,
                         cudaFuncAttributeMaxDynamicSharedMemorySize, SMEM_GEMM);
    cudaFuncSetAttribute(gemm_lin16<false>,
                         cudaFuncAttributeMaxDynamicSharedMemorySize, SMEM_GEMM);
    cudaFuncSetAttribute(gemm_lstm16<false>,
                         cudaFuncAttributeMaxDynamicSharedMemorySize, SMEM_LSTM);
    cudaFuncSetAttribute(gemm_lstm16<true>,
                         cudaFuncAttributeMaxDynamicSharedMemorySize, SMEM_LSTM);

    // ---- 1: weight linears (7 segs) ----
    {
        CvtSegs cs{};
        cs.src[0] = W_lt;     cs.dst[0] = w16 + O_WLT;   cs.n[0] = 512 * 768;
        cs.src[1] = W_li;     cs.dst[1] = w16 + O_WLI;   cs.n[1] = 512 * 2048;
        cs.src[2] = W_lo;     cs.dst[2] = w16 + O_WLO;   cs.n[2] = 512 * 512;
        cs.src[3] = ua_lin_W; cs.dst[3] = w16 + O_UALIN; cs.n[3] = 512 * 2000;
        cs.src[4] = pa_lin_W; cs.dst[4] = w16 + O_PALIN; cs.n[4] = 512 * 2000;
        cs.src[5] = ua_out_W; cs.dst[5] = w16 + O_UAOUT; cs.n[5] = 2000 * 2000;
        cs.src[6] = pa_out_W; cs.dst[6] = w16 + O_PAOUT; cs.n[6] = 2000 * 2000;
        int gx = (2000 * 2000 / 8 + 255) / 256;
        cvt_many<<<dim3(gx, 1, 7), 256>>>(cs);
    }
    // ---- 2: lstm weight gathers (5 via z) ----
    {
        Lstm5 ws{ { lstm_t_W, lstm_i_W, lstm_o_W, ua_lstm_W, pa_lstm_W } };
        int gx = (3 * 2000 * 512 / 8 + 255) / 256;
        cvt_lstm5<<<dim3(gx, 1, 5), 256>>>(ws, w16);
    }
    // ---- 3: inputs (6 segs) ----
    {
        CvtSegs cs{};
        cs.src[0] = c_text;  cs.dst[0] = in16 + I_TEXT;                    cs.n[0] = BB * 768;
        cs.src[1] = p_text;  cs.dst[1] = in16 + I_TEXT + BB * 768;         cs.n[1] = MPU * 768;
        cs.src[2] = u_text;  cs.dst[2] = in16 + I_TEXT + (BB + MPU) * 768; cs.n[2] = MPU * 768;
        cs.src[3] = c_image; cs.dst[3] = in16 + I_IMG;                     cs.n[3] = BB * 2048;
        cs.src[4] = p_image; cs.dst[4] = in16 + I_IMG + BB * 2048;         cs.n[4] = MPU * 2048;
        cs.src[5] = u_other; cs.dst[5] = in16 + I_OTH;                     cs.n[5] = MPU * 512;
        int gx = (MPU * 2048 / 8 + 255) / 256;
        cvt_many<<<dim3(gx, 1, 6), 256>>>(cs);
    }

    // ---- 4: all three input linears, one z=3 launch (N=512) ----
    {
        LinSet a{in16 + I_TEXT, w16 + O_WLT, b_lt, nullptr, bufX + X_TEXT, MT, 768};
        LinSet b{in16 + I_IMG,  w16 + O_WLI, b_li, nullptr, bufX + X_IMG,  MI2, 2048};
        LinSet c{in16 + I_OTH,  w16 + O_WLO, b_lo, nullptr, bufX + X_OTH,  MPU, 512};
        gemm_lin16<true><<<dim3(4, MT / 128, 3), 256, SMEM_GEMM>>>(a, b, c, 512);
    }
    // ---- 5: text LSTM -> Ht16 fp16 ----
    {
        LstmSet t{bufX + X_TEXT, w16 + O_LT, lstm_t_b, nullptr, nullptr, Ht16,
                  MT, 0};
        gemm_lstm16<false><<<dim3(32, MT / 64, 1), 256, SMEM_LSTM>>>(t, t, 0.5f);
    }
    // ---- 6: image LSTM (split Hc/Hp16) + other LSTM (Hu16), z=2, fp16 accum --
    {
        LstmSet im{bufX + X_IMG, w16 + O_LT + 1 * 3072000, lstm_i_b, Ht16,
                   Hc, Hp16, MI2, BB};
        LstmSet ot{bufX + X_OTH, w16 + O_LT + 2 * 3072000, lstm_o_b,
                   Ht16 + (size_t)MI2 * EE, nullptr, Hu16, MPU, 0};
        gemm_lstm16<true><<<dim3(32, MI2 / 64, 2), 256, SMEM_LSTM>>>(im, ot, 0.5f);
    }
    // ---- 7: paired agg linears (z=2, N=512, K=2000) ----
    {
        LinSet a{Hu16, w16 + O_UALIN, ua_lin_b, nullptr, bufX, MPU, 2000};
        LinSet b{Hp16, w16 + O_PALIN, pa_lin_b, nullptr, bufX + (size_t)MPU * 512,
                 MPU, 2000};
        gemm_lin16<true><<<dim3(4, MPU / 128, 2), 256, SMEM_GEMM>>>(a, b, b, 512);
    }
    // ---- 8: paired agg LSTMs (z=2) ----
    {
        LstmSet a{bufX, w16 + O_LT + 3 * 3072000, ua_lstm_b, nullptr, nullptr, H2,
                  MPU, 0};
        LstmSet b{bufX + (size_t)MPU * 512, w16 + O_LT + 4 * 3072000, pa_lstm_b,
                  nullptr, nullptr, H2 + (size_t)MPU * EE, MPU, 0};
        gemm_lstm16<false><<<dim3(32, MPU / 64, 2), 256, SMEM_LSTM>>>(a, b, 1.0f);
    }
    // ---- 9: paired neighbor mean (vectorized) ----
    mean16<<<(2 * BB * EE / 8 + 255) / 256, 256>>>(H2, Hm);
    // ---- 10: paired out-linears (z=2, N=2000, fp32 out) ----
    {
        LinSet a{Hm, w16 + O_UAOUT, ua_out_b, uagg, nullptr, BB, 2000};
        LinSet b{Hm + (size_t)BB * EE, w16 + O_PAOUT, pa_out_b, pagg, nullptr,
                 BB, 2000};
        gemm_lin16<false><<<dim3(16, BB / 128, 2), 256, SMEM_GEMM>>>(a, b, b, 2000);
    }
    // ---- 11: attention combine ----
    attention_kernel<<<BB, 256>>>(Hc, uagg, pagg, p_att, out);
}